// round 4
// baseline (speedup 1.0000x reference)
#include <cuda_runtime.h>
#include <math.h>

// ============================================================================
// tensor_field_net — GB300
//
// Shortcut: attn = e/(e+1e-10), e = exp(d/12), d unit-scale  =>  attn == 1
// to ~1e-9 relative. So out = elu(FCTP(x, x, w_v)); q/k/dot skipped entirely.
//
// Wigner-3j (e3nn real basis) recomputed on device each launch in fp64.
// ============================================================================

#define MUL            16
#define FEAT           144
#define NODES_PER_CTA  32
#define CTA_THREADS    128     // 4 threads per node
#define XSTRIDE        148     // 144 + 4 pad  (148 % 32 = 20 -> distinct banks across nodes)
#define BSTRIDE        260     // 256 + 4 pad  (260 % 32 = 4  -> distinct banks across nodes)
#define SMEM_FLOATS    (NODES_PER_CTA*XSTRIDE + NODES_PER_CTA*BSTRIDE + 4096 + 363)
#define SMEM_BYTES     (SMEM_FLOATS * 4)

// Concatenated real-w3j table in PATHS order:
// (0,0,0)(1,1,0)(2,2,0)(0,1,1)(1,0,1)(1,2,1)(2,1,1)(0,2,2)(1,1,2)(2,0,2)(2,2,2)
__device__ float g_w3j[363];

__constant__ int c_path_l[11][3] = {
    {0,0,0},{1,1,0},{2,2,0},{0,1,1},{1,0,1},{1,2,1},{2,1,1},{0,2,2},{1,1,2},{2,0,2},{2,2,2}};
__constant__ int c_path_off[11] = {0,1,10,35,44,53,98,143,168,213,238};

// ---------------------------------------------------------------------------
// Wigner-3j init (fp64, faithful translation of the reference precompute)
// ---------------------------------------------------------------------------
__device__ double d_fact(int n) {
    double r = 1.0;
    for (int i = 2; i <= n; i++) r *= (double)i;
    return r;
}

__device__ double su2_cg(int j1, int m1, int j2, int m2, int j3, int m3) {
    if (m3 != m1 + m2) return 0.0;
    int vmin = max(max(-j1 + j2 + m3, -j1 + m1), 0);
    int vmax = min(min(j2 + j3 + m1, j3 - j1 + j2), j3 + m3);
    if (vmax < vmin) return 0.0;
    double C = sqrt((2.0*j3 + 1.0) * d_fact(j3 + j1 - j2) * d_fact(j3 - j1 + j2) *
                    d_fact(j1 + j2 - j3) * d_fact(j3 + m3) * d_fact(j3 - m3) /
                    (d_fact(j1 + j2 + j3 + 1) * d_fact(j1 - m1) * d_fact(j1 + m1) *
                     d_fact(j2 - m2) * d_fact(j2 + m2)));
    double S = 0.0;
    for (int v = vmin; v <= vmax; v++) {
        double term = d_fact(j2 + j3 + m1 - v) * d_fact(j1 - m1 + v) /
                      (d_fact(v) * d_fact(j3 - j1 + j2 - v) * d_fact(j3 + m3 - v) *
                       d_fact(v + j1 - j2 - m3));
        S += (((v + j2 + m2) & 1) ? -term : term);
    }
    return C * S;
}

__device__ void qmat(int l, double* qr, double* qi) {
    int d = 2*l + 1;
    for (int a = 0; a < d*d; a++) { qr[a] = 0.0; qi[a] = 0.0; }
    double s = 1.0 / sqrt(2.0);
    for (int m = -l; m < 0; m++) {
        qr[(l + m)*d + (l - m)] = s;     // 1/sqrt2 at col l+|m|
        qi[(l + m)*d + (l + m)] = -s;    // -i/sqrt2 at col l-|m|
    }
    qr[l*d + l] = 1.0;
    for (int m = 1; m <= l; m++) {
        double sg = (m & 1) ? -1.0 : 1.0;
        qr[(l + m)*d + (l + m)] = sg * s;   // (-1)^m/sqrt2 at col l+m
        qi[(l + m)*d + (l - m)] = sg * s;   // i*(-1)^m/sqrt2 at col l-m
    }
    // multiply all by (-i)^l
    int r = l & 3;
    double fr, fi;
    if      (r == 0) { fr = 1.0;  fi = 0.0;  }
    else if (r == 1) { fr = 0.0;  fi = -1.0; }
    else if (r == 2) { fr = -1.0; fi = 0.0;  }
    else             { fr = 0.0;  fi = 1.0;  }
    for (int a = 0; a < d*d; a++) {
        double nr = qr[a]*fr - qi[a]*fi;
        double ni = qr[a]*fi + qi[a]*fr;
        qr[a] = nr; qi[a] = ni;
    }
}

__global__ void w3j_init_kernel() {
    const int p  = blockIdx.x;
    const int l1 = c_path_l[p][0], l2 = c_path_l[p][1], l3 = c_path_l[p][2];
    const int d1 = 2*l1 + 1, d2 = 2*l2 + 1, d3 = 2*l3 + 1;
    const int n_el = d1 * d2 * d3;

    __shared__ double Ccg[125];
    __shared__ double Crr[125];
    __shared__ double q1r[25], q1i[25], q2r[25], q2i[25], q3r[25], q3i[25];
    __shared__ double red[64];

    int tid = threadIdx.x;  // 64 threads

    for (int idx = tid; idx < n_el; idx += 64) {
        int i  = idx / (d2*d3);
        int r  = idx % (d2*d3);
        int kq = r / d3;
        int nq = r % d3;
        Ccg[idx] = su2_cg(l1, i - l1, l2, kq - l2, l3, nq - l3);
    }
    if (tid == 0) qmat(l1, q1r, q1i);
    if (tid == 1) qmat(l2, q2r, q2i);
    if (tid == 2) qmat(l3, q3r, q3i);
    __syncthreads();

    // Cr[j,l,m] = Re( sum_{i,k,n} q1[i,j] q2[k,l] conj(q3[n,m]) C[i,k,n] )
    double ss = 0.0;
    for (int idx = tid; idx < n_el; idx += 64) {
        int j  = idx / (d2*d3);
        int r  = idx % (d2*d3);
        int lc = r / d3;
        int m  = r % d3;
        double sre = 0.0;
        for (int i = 0; i < d1; i++)
            for (int kq = 0; kq < d2; kq++)
                for (int nq = 0; nq < d3; nq++) {
                    double c = Ccg[(i*d2 + kq)*d3 + nq];
                    if (c == 0.0) continue;
                    double ar = q1r[i*d1 + j],   ai = q1i[i*d1 + j];
                    double br = q2r[kq*d2 + lc], bi = q2i[kq*d2 + lc];
                    double cr = q3r[nq*d3 + m],  ci = q3i[nq*d3 + m];
                    double tr = ar*br - ai*bi;
                    double ti = ar*bi + ai*br;
                    sre += (tr*cr + ti*ci) * c;   // Re(t * conj(q3[n,m])) * C
                }
        Crr[idx] = sre;
        ss += sre * sre;
    }
    red[tid] = ss;
    __syncthreads();
    for (int s = 32; s > 0; s >>= 1) {
        if (tid < s) red[tid] += red[tid + s];
        __syncthreads();
    }
    double inv = rsqrt(red[0]);
    for (int idx = tid; idx < n_el; idx += 64)
        g_w3j[c_path_off[p] + idx] = (float)(Crr[idx] * inv);
}

// ---------------------------------------------------------------------------
// Main fused FCTP(v) + elu kernel
// 4 threads per node; thread t owns w in {4t..4t+3} (float4 W loads) and
// v in {t, t+4, t+8, t+12} for the b-stage.
// ---------------------------------------------------------------------------
template<int L1, int L2, int L3, int BASE>
__device__ __forceinline__ void path_accum(
    const float* __restrict__ xn,   // this node's x in smem (144 used)
    float*       __restrict__ bn,   // this node's b_k scratch (256 used)
    const float* __restrict__ sW,   // current path weights [(u*16+v)*16 + w]
    const float* __restrict__ cg,   // w3j slice, [(i*D2+j)*D3 + k]
    int t, float* __restrict__ acc)
{
    constexpr int D1 = 2*L1 + 1, D2 = 2*L2 + 1, D3 = 2*L3 + 1;
    constexpr int O1 = (L1 == 0) ? 0 : ((L1 == 1) ? 16 : 64);
    constexpr int O2 = (L2 == 0) ? 0 : ((L2 == 1) ? 16 : 64);

    #pragma unroll
    for (int k = 0; k < D3; k++) {
        // a[i][z] for v = t + 4z :  a[i,v] = sum_j x2[v,j] * C[i,j,k]
        float a[D1 * 4];
        #pragma unroll
        for (int z = 0; z < D1*4; z++) a[z] = 0.f;
        #pragma unroll
        for (int j = 0; j < D2; j++) {
            float xv0 = xn[O2 + (t     )*D2 + j];
            float xv1 = xn[O2 + (t + 4 )*D2 + j];
            float xv2 = xn[O2 + (t + 8 )*D2 + j];
            float xv3 = xn[O2 + (t + 12)*D2 + j];
            #pragma unroll
            for (int i = 0; i < D1; i++) {
                float c = cg[(i*D2 + j)*D3 + k];
                a[i*4 + 0] = fmaf(c, xv0, a[i*4 + 0]);
                a[i*4 + 1] = fmaf(c, xv1, a[i*4 + 1]);
                a[i*4 + 2] = fmaf(c, xv2, a[i*4 + 2]);
                a[i*4 + 3] = fmaf(c, xv3, a[i*4 + 3]);
            }
        }
        // b_k[u,v] = sum_i x1[u,i] * a[i,v]
        #pragma unroll 4
        for (int u = 0; u < 16; u++) {
            float b0 = 0.f, b1 = 0.f, b2 = 0.f, b3 = 0.f;
            #pragma unroll
            for (int i = 0; i < D1; i++) {
                float x1 = xn[O1 + u*D1 + i];
                b0 = fmaf(x1, a[i*4 + 0], b0);
                b1 = fmaf(x1, a[i*4 + 1], b1);
                b2 = fmaf(x1, a[i*4 + 2], b2);
                b3 = fmaf(x1, a[i*4 + 3], b3);
            }
            bn[u*16 + t     ] = b0;
            bn[u*16 + t + 4 ] = b1;
            bn[u*16 + t + 8 ] = b2;
            bn[u*16 + t + 12] = b3;
        }
        __syncwarp();
        // o[w,k] += sum_uv W[u,v,w] * b_k[u,v]   (hot loop, FMA-bound)
        float s0 = 0.f, s1 = 0.f, s2 = 0.f, s3 = 0.f;
        #pragma unroll 8
        for (int uv = 0; uv < 256; uv++) {
            float4 w4 = *(const float4*)(sW + uv*16 + 4*t);
            float  bv = bn[uv];
            s0 = fmaf(w4.x, bv, s0);
            s1 = fmaf(w4.y, bv, s1);
            s2 = fmaf(w4.z, bv, s2);
            s3 = fmaf(w4.w, bv, s3);
        }
        acc[BASE + k*4 + 0] += s0;
        acc[BASE + k*4 + 1] += s1;
        acc[BASE + k*4 + 2] += s2;
        acc[BASE + k*4 + 3] += s3;
        __syncwarp();   // WAR: contraction reads done before next slice's b writes
    }
}

__global__ void __launch_bounds__(CTA_THREADS, 3)
tfn_kernel(const float* __restrict__ x, const float* __restrict__ wv,
           float* __restrict__ out, int N)
{
    extern __shared__ float smem[];
    float* xs  = smem;
    float* bs  = xs + NODES_PER_CTA * XSTRIDE;
    float* sW  = bs + NODES_PER_CTA * BSTRIDE;
    float* scg = sW + 4096;

    const int tid = threadIdx.x;
    const int n0  = blockIdx.x * NODES_PER_CTA;

    // Load x tiles (float4, coalesced); zero-fill out-of-range nodes.
    for (int idx = tid; idx < NODES_PER_CTA * 36; idx += CTA_THREADS) {
        int n = idx / 36, f = idx % 36;
        int gn = n0 + n;
        float4 v = (gn < N) ? ((const float4*)x)[gn*36 + f]
                            : make_float4(0.f, 0.f, 0.f, 0.f);
        *(float4*)(xs + n*XSTRIDE + f*4) = v;
    }
    for (int idx = tid; idx < 363; idx += CTA_THREADS)
        scg[idx] = g_w3j[idx];

    const int node = tid >> 2;
    const int t    = tid & 3;
    const float* xn = xs + node * XSTRIDE;
    float*       bn = bs + node * BSTRIDE;

    // acc layout: [0..3]=l3=0(k=0), [4..15]=l3=1(k*4+i), [16..35]=l3=2(k*4+i)
    float acc[36];
    #pragma unroll
    for (int i = 0; i < 36; i++) acc[i] = 0.f;

#define DO_PATH(P, L1, L2, L3, BASE, OFF)                                   \
    __syncthreads();                                                        \
    {                                                                       \
        const float4* wg  = (const float4*)(wv + (P)*4096);                 \
        float4*       sw4 = (float4*)sW;                                    \
        for (int idx = tid; idx < 1024; idx += CTA_THREADS)                 \
            sw4[idx] = wg[idx];                                             \
    }                                                                       \
    __syncthreads();                                                        \
    path_accum<L1, L2, L3, BASE>(xn, bn, sW, scg + (OFF), t, acc);

    DO_PATH(0,  0,0,0,  0,   0)
    DO_PATH(1,  1,1,0,  0,   1)
    DO_PATH(2,  2,2,0,  0,   10)
    DO_PATH(3,  0,1,1,  4,   35)
    DO_PATH(4,  1,0,1,  4,   44)
    DO_PATH(5,  1,2,1,  4,   53)
    DO_PATH(6,  2,1,1,  4,   98)
    DO_PATH(7,  0,2,2,  16,  143)
    DO_PATH(8,  1,1,2,  16,  168)
    DO_PATH(9,  2,0,2,  16,  213)
    DO_PATH(10, 2,2,2,  16,  238)
#undef DO_PATH

    const int gn = n0 + node;
    if (gn < N) {
        // scale = sqrt((2*l3+1) / (n_paths[l3] * MUL * MUL))
        const float sc0 = 0.03608439182435161f;   // sqrt(1/768)
        const float sc1 = 0.05412658773652741f;   // sqrt(3/1024)
        const float sc2 = 0.06987712429686843f;   // sqrt(5/1024)
        float* o = out + (size_t)gn * FEAT;
        #pragma unroll
        for (int i = 0; i < 4; i++) {
            int w = 4*t + i;
            float v = acc[i] * sc0;
            o[w] = v > 0.f ? v : (expf(v) - 1.f);
        }
        #pragma unroll
        for (int k = 0; k < 3; k++) {
            #pragma unroll
            for (int i = 0; i < 4; i++) {
                int w = 4*t + i;
                float v = acc[4 + k*4 + i] * sc1;
                o[16 + w*3 + k] = v > 0.f ? v : (expf(v) - 1.f);
            }
        }
        #pragma unroll
        for (int k = 0; k < 5; k++) {
            #pragma unroll
            for (int i = 0; i < 4; i++) {
                int w = 4*t + i;
                float v = acc[16 + k*4 + i] * sc2;
                o[64 + w*5 + k] = v > 0.f ? v : (expf(v) - 1.f);
            }
        }
    }
}

// ---------------------------------------------------------------------------
extern "C" void kernel_launch(void* const* d_in, const int* in_sizes, int n_in,
                              void* d_out, int out_size)
{
    const float* x  = (const float*)d_in[0];   // nodes_features [N,144]
    const float* wv = (const float*)d_in[6];   // w_v [11,16,16,16]
    float* out = (float*)d_out;                // [9N,16] == [N,144]
    const int N = in_sizes[0] / FEAT;

    cudaFuncSetAttribute(tfn_kernel,
                         cudaFuncAttributeMaxDynamicSharedMemorySize, SMEM_BYTES);

    w3j_init_kernel<<<11, 64>>>();
    const int grid = (N + NODES_PER_CTA - 1) / NODES_PER_CTA;
    tfn_kernel<<<grid, CTA_THREADS, SMEM_BYTES>>>(x, wv, out, N);
}

// round 5
// speedup vs baseline: 1.0917x; 1.0917x over previous
#include <cuda_runtime.h>
#include <math.h>

// ============================================================================
// tensor_field_net — GB300
//
// Shortcut: attn = e/(e+1e-10), e = exp(d/12), d unit-scale  =>  attn == 1
// to ~1e-9 relative. So out = elu(FCTP(x, x, w_v)); q/k/dot skipped entirely.
//
// Hot contraction uses Blackwell packed fp32 (fma.rn.f32x2) + k-pair batching
// to relieve the shared-memory pipe (88% in R3 profile).
// ============================================================================

#define MUL            16
#define FEAT           144
#define NODES_PER_CTA  32
#define CTA_THREADS    128     // 4 threads per node
#define XSTRIDE        148     // floats; 148%32=20 -> node bases on distinct banks
#define BSTRIDE        516     // floats; 516%32=4, 516*4B 16B-aligned
#define SW_FLOATS      4096
#define SMEM_FLOATS    (NODES_PER_CTA*XSTRIDE + NODES_PER_CTA*BSTRIDE + SW_FLOATS + 364)
#define SMEM_BYTES     (SMEM_FLOATS * 4)

// Concatenated real-w3j table in PATHS order:
// (0,0,0)(1,1,0)(2,2,0)(0,1,1)(1,0,1)(1,2,1)(2,1,1)(0,2,2)(1,1,2)(2,0,2)(2,2,2)
__device__ float g_w3j[363];

__constant__ int c_path_l[11][3] = {
    {0,0,0},{1,1,0},{2,2,0},{0,1,1},{1,0,1},{1,2,1},{2,1,1},{0,2,2},{1,1,2},{2,0,2},{2,2,2}};
__constant__ int c_path_off[11] = {0,1,10,35,44,53,98,143,168,213,238};

// ---------------------------------------------------------------------------
// f32x2 helpers (packed fp32 pair in one 64-bit register)
// ---------------------------------------------------------------------------
__device__ __forceinline__ unsigned long long pack2(float lo, float hi) {
    unsigned long long r;
    asm("mov.b64 %0, {%1, %2};" : "=l"(r)
        : "r"(__float_as_uint(lo)), "r"(__float_as_uint(hi)));
    return r;
}
__device__ __forceinline__ void unpack2(unsigned long long p, float& lo, float& hi) {
    unsigned int a, b;
    asm("mov.b64 {%0, %1}, %2;" : "=r"(a), "=r"(b) : "l"(p));
    lo = __uint_as_float(a); hi = __uint_as_float(b);
}
__device__ __forceinline__ void ffma2(unsigned long long& acc,
                                      unsigned long long a, unsigned long long b) {
    asm("fma.rn.f32x2 %0, %1, %2, %0;" : "+l"(acc) : "l"(a), "l"(b));
}

// ---------------------------------------------------------------------------
// Wigner-3j init (fp64, faithful translation of the reference precompute)
// ---------------------------------------------------------------------------
__device__ double d_fact(int n) {
    double r = 1.0;
    for (int i = 2; i <= n; i++) r *= (double)i;
    return r;
}

__device__ double su2_cg(int j1, int m1, int j2, int m2, int j3, int m3) {
    if (m3 != m1 + m2) return 0.0;
    int vmin = max(max(-j1 + j2 + m3, -j1 + m1), 0);
    int vmax = min(min(j2 + j3 + m1, j3 - j1 + j2), j3 + m3);
    if (vmax < vmin) return 0.0;
    double C = sqrt((2.0*j3 + 1.0) * d_fact(j3 + j1 - j2) * d_fact(j3 - j1 + j2) *
                    d_fact(j1 + j2 - j3) * d_fact(j3 + m3) * d_fact(j3 - m3) /
                    (d_fact(j1 + j2 + j3 + 1) * d_fact(j1 - m1) * d_fact(j1 + m1) *
                     d_fact(j2 - m2) * d_fact(j2 + m2)));
    double S = 0.0;
    for (int v = vmin; v <= vmax; v++) {
        double term = d_fact(j2 + j3 + m1 - v) * d_fact(j1 - m1 + v) /
                      (d_fact(v) * d_fact(j3 - j1 + j2 - v) * d_fact(j3 + m3 - v) *
                       d_fact(v + j1 - j2 - m3));
        S += (((v + j2 + m2) & 1) ? -term : term);
    }
    return C * S;
}

__device__ void qmat(int l, double* qr, double* qi) {
    int d = 2*l + 1;
    for (int a = 0; a < d*d; a++) { qr[a] = 0.0; qi[a] = 0.0; }
    double s = 1.0 / sqrt(2.0);
    for (int m = -l; m < 0; m++) {
        qr[(l + m)*d + (l - m)] = s;
        qi[(l + m)*d + (l + m)] = -s;
    }
    qr[l*d + l] = 1.0;
    for (int m = 1; m <= l; m++) {
        double sg = (m & 1) ? -1.0 : 1.0;
        qr[(l + m)*d + (l + m)] = sg * s;
        qi[(l + m)*d + (l - m)] = sg * s;
    }
    int r = l & 3;
    double fr, fi;
    if      (r == 0) { fr = 1.0;  fi = 0.0;  }
    else if (r == 1) { fr = 0.0;  fi = -1.0; }
    else if (r == 2) { fr = -1.0; fi = 0.0;  }
    else             { fr = 0.0;  fi = 1.0;  }
    for (int a = 0; a < d*d; a++) {
        double nr = qr[a]*fr - qi[a]*fi;
        double ni = qr[a]*fi + qi[a]*fr;
        qr[a] = nr; qi[a] = ni;
    }
}

__global__ void w3j_init_kernel() {
    const int p  = blockIdx.x;
    const int l1 = c_path_l[p][0], l2 = c_path_l[p][1], l3 = c_path_l[p][2];
    const int d1 = 2*l1 + 1, d2 = 2*l2 + 1, d3 = 2*l3 + 1;
    const int n_el = d1 * d2 * d3;

    __shared__ double Ccg[125];
    __shared__ double Crr[125];
    __shared__ double q1r[25], q1i[25], q2r[25], q2i[25], q3r[25], q3i[25];
    __shared__ double red[64];

    int tid = threadIdx.x;  // 64 threads

    for (int idx = tid; idx < n_el; idx += 64) {
        int i  = idx / (d2*d3);
        int r  = idx % (d2*d3);
        int kq = r / d3;
        int nq = r % d3;
        Ccg[idx] = su2_cg(l1, i - l1, l2, kq - l2, l3, nq - l3);
    }
    if (tid == 0) qmat(l1, q1r, q1i);
    if (tid == 1) qmat(l2, q2r, q2i);
    if (tid == 2) qmat(l3, q3r, q3i);
    __syncthreads();

    double ss = 0.0;
    for (int idx = tid; idx < n_el; idx += 64) {
        int j  = idx / (d2*d3);
        int r  = idx % (d2*d3);
        int lc = r / d3;
        int m  = r % d3;
        double sre = 0.0;
        for (int i = 0; i < d1; i++)
            for (int kq = 0; kq < d2; kq++)
                for (int nq = 0; nq < d3; nq++) {
                    double c = Ccg[(i*d2 + kq)*d3 + nq];
                    if (c == 0.0) continue;
                    double ar = q1r[i*d1 + j],   ai = q1i[i*d1 + j];
                    double br = q2r[kq*d2 + lc], bi = q2i[kq*d2 + lc];
                    double cr = q3r[nq*d3 + m],  ci = q3i[nq*d3 + m];
                    double tr = ar*br - ai*bi;
                    double ti = ar*bi + ai*br;
                    sre += (tr*cr + ti*ci) * c;
                }
        Crr[idx] = sre;
        ss += sre * sre;
    }
    red[tid] = ss;
    __syncthreads();
    for (int s = 32; s > 0; s >>= 1) {
        if (tid < s) red[tid] += red[tid + s];
        __syncthreads();
    }
    double inv = rsqrt(red[0]);
    for (int idx = tid; idx < n_el; idx += 64)
        g_w3j[c_path_off[p] + idx] = (float)(Crr[idx] * inv);
}

// ---------------------------------------------------------------------------
// Per-path accumulation. 4 threads/node; thread t owns w in {4t..4t+3} and
// computes b for v in {4t..4t+3}. k-slices processed in pairs, f32x2 packed.
// bn layouts: pair chunks: bn[uv*2 + kk]; single chunk: bn[uv].
// ---------------------------------------------------------------------------
template<int L1, int L2, int L3, int BASE>
__device__ __forceinline__ void path_accum(
    const float* __restrict__ xn, float* __restrict__ bn,
    const float* __restrict__ sW, const float* __restrict__ cg,
    int t, float* __restrict__ acc)
{
    constexpr int D1 = 2*L1 + 1, D2 = 2*L2 + 1, D3 = 2*L3 + 1;
    constexpr int O1 = (L1 == 0) ? 0 : ((L1 == 1) ? 16 : 64);
    constexpr int O2 = (L2 == 0) ? 0 : ((L2 == 1) ? 16 : 64);

    // x2 rows for the owned v's — reused across all k of this path
    float xv[4][D2];
    #pragma unroll
    for (int z = 0; z < 4; z++)
        #pragma unroll
        for (int j = 0; j < D2; j++)
            xv[z][j] = xn[O2 + (4*t + z)*D2 + j];

    // ---- k-pair chunks ----
    #pragma unroll
    for (int k0 = 0; k0 + 1 < D3; k0 += 2) {
        // a2[i*4+z] = (a_{k0}[i,v], a_{k0+1}[i,v]) packed
        unsigned long long a2[D1*4];
        #pragma unroll
        for (int q = 0; q < D1*4; q++) a2[q] = 0ull;
        #pragma unroll
        for (int j = 0; j < D2; j++) {
            unsigned long long xd[4];
            #pragma unroll
            for (int z = 0; z < 4; z++) xd[z] = pack2(xv[z][j], xv[z][j]);
            #pragma unroll
            for (int i = 0; i < D1; i++) {
                float c0 = cg[(i*D2 + j)*D3 + k0];
                float c1 = cg[(i*D2 + j)*D3 + k0 + 1];
                unsigned long long cp = pack2(c0, c1);
                #pragma unroll
                for (int z = 0; z < 4; z++) ffma2(a2[i*4 + z], cp, xd[z]);
            }
        }
        // b stage: bb[z] = (b_k0[u, 4t+z], b_k1[u, 4t+z])
        #pragma unroll 2
        for (int u = 0; u < 16; u++) {
            unsigned long long bb[4] = {0ull, 0ull, 0ull, 0ull};
            #pragma unroll
            for (int i = 0; i < D1; i++) {
                float x1 = xn[O1 + u*D1 + i];
                unsigned long long xp = pack2(x1, x1);
                #pragma unroll
                for (int z = 0; z < 4; z++) ffma2(bb[z], xp, a2[i*4 + z]);
            }
            *(ulonglong2*)(bn + u*32 + 8*t)     = make_ulonglong2(bb[0], bb[1]);
            *(ulonglong2*)(bn + u*32 + 8*t + 4) = make_ulonglong2(bb[2], bb[3]);
        }
        __syncwarp();
        // contraction: accA=(o[w0],o[w1])@k0  accB=(o[w2],o[w3])@k0  C/D @k1
        unsigned long long accA = 0, accB = 0, accC = 0, accD = 0;
        #pragma unroll 8
        for (int uv = 0; uv < 256; uv++) {
            ulonglong2 w2 = *(const ulonglong2*)(sW + uv*16 + 4*t);
            unsigned long long bp = *(const unsigned long long*)(bn + uv*2);
            unsigned int b0, b1;
            asm("mov.b64 {%0, %1}, %2;" : "=r"(b0), "=r"(b1) : "l"(bp));
            unsigned long long b00, b11;
            asm("mov.b64 %0, {%1, %1};" : "=l"(b00) : "r"(b0));
            asm("mov.b64 %0, {%1, %1};" : "=l"(b11) : "r"(b1));
            ffma2(accA, w2.x, b00);
            ffma2(accB, w2.y, b00);
            ffma2(accC, w2.x, b11);
            ffma2(accD, w2.y, b11);
        }
        float lo, hi;
        unpack2(accA, lo, hi); acc[BASE + k0*4 + 0] += lo; acc[BASE + k0*4 + 1] += hi;
        unpack2(accB, lo, hi); acc[BASE + k0*4 + 2] += lo; acc[BASE + k0*4 + 3] += hi;
        unpack2(accC, lo, hi); acc[BASE + (k0+1)*4 + 0] += lo; acc[BASE + (k0+1)*4 + 1] += hi;
        unpack2(accD, lo, hi); acc[BASE + (k0+1)*4 + 2] += lo; acc[BASE + (k0+1)*4 + 3] += hi;
        __syncwarp();
    }

    // ---- remainder single k (D3 is odd: always one) ----
    {
        constexpr int k = D3 - 1;
        float a[D1*4];
        #pragma unroll
        for (int q = 0; q < D1*4; q++) a[q] = 0.f;
        #pragma unroll
        for (int j = 0; j < D2; j++) {
            #pragma unroll
            for (int i = 0; i < D1; i++) {
                float c = cg[(i*D2 + j)*D3 + k];
                #pragma unroll
                for (int z = 0; z < 4; z++) a[i*4 + z] = fmaf(c, xv[z][j], a[i*4 + z]);
            }
        }
        #pragma unroll 2
        for (int u = 0; u < 16; u++) {
            float b[4] = {0.f, 0.f, 0.f, 0.f};
            #pragma unroll
            for (int i = 0; i < D1; i++) {
                float x1 = xn[O1 + u*D1 + i];
                #pragma unroll
                for (int z = 0; z < 4; z++) b[z] = fmaf(x1, a[i*4 + z], b[z]);
            }
            *(float4*)(bn + u*16 + 4*t) = make_float4(b[0], b[1], b[2], b[3]);
        }
        __syncwarp();
        unsigned long long accA = 0, accB = 0;
        #pragma unroll 8
        for (int uv = 0; uv < 256; uv++) {
            ulonglong2 w2 = *(const ulonglong2*)(sW + uv*16 + 4*t);
            float bv = bn[uv];
            unsigned long long bbv;
            asm("mov.b64 %0, {%1, %1};" : "=l"(bbv) : "r"(__float_as_uint(bv)));
            ffma2(accA, w2.x, bbv);
            ffma2(accB, w2.y, bbv);
        }
        float lo, hi;
        unpack2(accA, lo, hi); acc[BASE + k*4 + 0] += lo; acc[BASE + k*4 + 1] += hi;
        unpack2(accB, lo, hi); acc[BASE + k*4 + 2] += lo; acc[BASE + k*4 + 3] += hi;
        __syncwarp();
    }
}

__global__ void __launch_bounds__(CTA_THREADS, 2)
tfn_kernel(const float* __restrict__ x, const float* __restrict__ wv,
           float* __restrict__ out, int N)
{
    extern __shared__ float smem[];
    float* xs  = smem;
    float* bs  = xs + NODES_PER_CTA * XSTRIDE;
    float* sW  = bs + NODES_PER_CTA * BSTRIDE;
    float* scg = sW + SW_FLOATS;

    const int tid = threadIdx.x;
    const int n0  = blockIdx.x * NODES_PER_CTA;

    for (int idx = tid; idx < NODES_PER_CTA * 36; idx += CTA_THREADS) {
        int n = idx / 36, f = idx % 36;
        int gn = n0 + n;
        float4 v = (gn < N) ? ((const float4*)x)[gn*36 + f]
                            : make_float4(0.f, 0.f, 0.f, 0.f);
        *(float4*)(xs + n*XSTRIDE + f*4) = v;
    }
    for (int idx = tid; idx < 363; idx += CTA_THREADS)
        scg[idx] = g_w3j[idx];

    const int node = tid >> 2;
    const int t    = tid & 3;
    const float* xn = xs + node * XSTRIDE;
    float*       bn = bs + node * BSTRIDE;

    // acc layout: [0..3]=l3=0, [4..15]=l3=1 (k*4+i), [16..35]=l3=2 (k*4+i)
    float acc[36];
    #pragma unroll
    for (int i = 0; i < 36; i++) acc[i] = 0.f;

#define DO_PATH(P, L1, L2, L3, BASE, OFF)                                   \
    __syncthreads();                                                        \
    {                                                                       \
        const float4* wg  = (const float4*)(wv + (P)*4096);                 \
        float4*       sw4 = (float4*)sW;                                    \
        for (int idx = tid; idx < 1024; idx += CTA_THREADS)                 \
            sw4[idx] = wg[idx];                                             \
    }                                                                       \
    __syncthreads();                                                        \
    path_accum<L1, L2, L3, BASE>(xn, bn, sW, scg + (OFF), t, acc);

    DO_PATH(0,  0,0,0,  0,   0)
    DO_PATH(1,  1,1,0,  0,   1)
    DO_PATH(2,  2,2,0,  0,   10)
    DO_PATH(3,  0,1,1,  4,   35)
    DO_PATH(4,  1,0,1,  4,   44)
    DO_PATH(5,  1,2,1,  4,   53)
    DO_PATH(6,  2,1,1,  4,   98)
    DO_PATH(7,  0,2,2,  16,  143)
    DO_PATH(8,  1,1,2,  16,  168)
    DO_PATH(9,  2,0,2,  16,  213)
    DO_PATH(10, 2,2,2,  16,  238)
#undef DO_PATH

    const int gn = n0 + node;
    if (gn < N) {
        const float sc0 = 0.03608439182435161f;   // sqrt(1/768)
        const float sc1 = 0.05412658773652741f;   // sqrt(3/1024)
        const float sc2 = 0.06987712429686843f;   // sqrt(5/1024)
        float* o = out + (size_t)gn * FEAT;
        #pragma unroll
        for (int i = 0; i < 4; i++) {
            int w = 4*t + i;
            float v = acc[i] * sc0;
            o[w] = v > 0.f ? v : (expf(v) - 1.f);
        }
        #pragma unroll
        for (int k = 0; k < 3; k++) {
            #pragma unroll
            for (int i = 0; i < 4; i++) {
                int w = 4*t + i;
                float v = acc[4 + k*4 + i] * sc1;
                o[16 + w*3 + k] = v > 0.f ? v : (expf(v) - 1.f);
            }
        }
        #pragma unroll
        for (int k = 0; k < 5; k++) {
            #pragma unroll
            for (int i = 0; i < 4; i++) {
                int w = 4*t + i;
                float v = acc[16 + k*4 + i] * sc2;
                o[64 + w*5 + k] = v > 0.f ? v : (expf(v) - 1.f);
            }
        }
    }
}

// ---------------------------------------------------------------------------
extern "C" void kernel_launch(void* const* d_in, const int* in_sizes, int n_in,
                              void* d_out, int out_size)
{
    const float* x  = (const float*)d_in[0];   // nodes_features [N,144]
    const float* wv = (const float*)d_in[6];   // w_v [11,16,16,16]
    float* out = (float*)d_out;                // [9N,16] == [N,144]
    const int N = in_sizes[0] / FEAT;

    cudaFuncSetAttribute(tfn_kernel,
                         cudaFuncAttributeMaxDynamicSharedMemorySize, SMEM_BYTES);

    w3j_init_kernel<<<11, 64>>>();
    const int grid = (N + NODES_PER_CTA - 1) / NODES_PER_CTA;
    tfn_kernel<<<grid, CTA_THREADS, SMEM_BYTES>>>(x, wv, out, N);
}

// round 6
// speedup vs baseline: 1.5457x; 1.4159x over previous
#include <cuda_runtime.h>
#include <math.h>

// ============================================================================
// tensor_field_net — GB300
//
// attn = e/(e+1e-10), e=exp(d/12), d unit-scale => attn==1 to ~1e-9.
// So out = elu(FCTP(x,x,w_v)); q/k/dot skipped.
//
// R5: register-resident b + shuffle-butterfly reduction (no smem b scratch),
// 8 threads/node, conflict-free stride-20 W tiles, k-pair-packed w3j table.
// ============================================================================

#define MUL            16
#define FEAT           144
#define NODES_PER_CTA  32
#define CTA_THREADS    256     // 8 threads per node
#define XSTRIDE        148
#define SW_STRIDE      20      // floats per (u,v) W row; banks {0,20,8,28,...} conflict-free
#define SMEM_FLOATS    (364 + NODES_PER_CTA*XSTRIDE + 256*SW_STRIDE)   // 10220
#define SMEM_BYTES     (SMEM_FLOATS * 4)

// w3j tables (filled by init kernel each launch):
//  pairs: per path, per k-pair p: [(p*D1*D2 + i*D2+j)] as float2 {C[..,2p],C[..,2p+1]}
//  last : per path: [i*D2+j] = C[..,D3-1]
__device__ float g_w3j_pairs[248];   // 124 float2
__device__ float g_w3j_last[115];

__constant__ int c_path_l[11][3] = {
    {0,0,0},{1,1,0},{2,2,0},{0,1,1},{1,0,1},{1,2,1},{2,1,1},{0,2,2},{1,1,2},{2,0,2},{2,2,2}};
__constant__ int c_pair_off[11] = {0,0,0,0,3,6,21,36,46,64,74};     // float2 units
__constant__ int c_last_off[11] = {0,1,10,35,38,41,56,71,76,85,90};

// ---------------------------------------------------------------------------
// f32x2 helpers
// ---------------------------------------------------------------------------
__device__ __forceinline__ unsigned long long pack2(float lo, float hi) {
    unsigned long long r;
    asm("mov.b64 %0, {%1, %2};" : "=l"(r)
        : "r"(__float_as_uint(lo)), "r"(__float_as_uint(hi)));
    return r;
}
__device__ __forceinline__ unsigned long long dup2(float v) {
    unsigned long long r;
    asm("mov.b64 %0, {%1, %1};" : "=l"(r) : "r"(__float_as_uint(v)));
    return r;
}
__device__ __forceinline__ void unpack2(unsigned long long p, float& lo, float& hi) {
    unsigned int a, b;
    asm("mov.b64 {%0, %1}, %2;" : "=r"(a), "=r"(b) : "l"(p));
    lo = __uint_as_float(a); hi = __uint_as_float(b);
}
__device__ __forceinline__ void ffma2(unsigned long long& acc,
                                      unsigned long long a, unsigned long long b) {
    asm("fma.rn.f32x2 %0, %1, %2, %0;" : "+l"(acc) : "l"(a), "l"(b));
}

// ---------------------------------------------------------------------------
// Wigner-3j init (fp64, faithful translation of the reference precompute)
// ---------------------------------------------------------------------------
__device__ double d_fact(int n) {
    double r = 1.0;
    for (int i = 2; i <= n; i++) r *= (double)i;
    return r;
}

__device__ double su2_cg(int j1, int m1, int j2, int m2, int j3, int m3) {
    if (m3 != m1 + m2) return 0.0;
    int vmin = max(max(-j1 + j2 + m3, -j1 + m1), 0);
    int vmax = min(min(j2 + j3 + m1, j3 - j1 + j2), j3 + m3);
    if (vmax < vmin) return 0.0;
    double C = sqrt((2.0*j3 + 1.0) * d_fact(j3 + j1 - j2) * d_fact(j3 - j1 + j2) *
                    d_fact(j1 + j2 - j3) * d_fact(j3 + m3) * d_fact(j3 - m3) /
                    (d_fact(j1 + j2 + j3 + 1) * d_fact(j1 - m1) * d_fact(j1 + m1) *
                     d_fact(j2 - m2) * d_fact(j2 + m2)));
    double S = 0.0;
    for (int v = vmin; v <= vmax; v++) {
        double term = d_fact(j2 + j3 + m1 - v) * d_fact(j1 - m1 + v) /
                      (d_fact(v) * d_fact(j3 - j1 + j2 - v) * d_fact(j3 + m3 - v) *
                       d_fact(v + j1 - j2 - m3));
        S += (((v + j2 + m2) & 1) ? -term : term);
    }
    return C * S;
}

__device__ void qmat(int l, double* qr, double* qi) {
    int d = 2*l + 1;
    for (int a = 0; a < d*d; a++) { qr[a] = 0.0; qi[a] = 0.0; }
    double s = 1.0 / sqrt(2.0);
    for (int m = -l; m < 0; m++) {
        qr[(l + m)*d + (l - m)] = s;
        qi[(l + m)*d + (l + m)] = -s;
    }
    qr[l*d + l] = 1.0;
    for (int m = 1; m <= l; m++) {
        double sg = (m & 1) ? -1.0 : 1.0;
        qr[(l + m)*d + (l + m)] = sg * s;
        qi[(l + m)*d + (l - m)] = sg * s;
    }
    int r = l & 3;
    double fr, fi;
    if      (r == 0) { fr = 1.0;  fi = 0.0;  }
    else if (r == 1) { fr = 0.0;  fi = -1.0; }
    else if (r == 2) { fr = -1.0; fi = 0.0;  }
    else             { fr = 0.0;  fi = 1.0;  }
    for (int a = 0; a < d*d; a++) {
        double nr = qr[a]*fr - qi[a]*fi;
        double ni = qr[a]*fi + qi[a]*fr;
        qr[a] = nr; qi[a] = ni;
    }
}

__global__ void w3j_init_kernel() {
    const int p  = blockIdx.x;
    const int l1 = c_path_l[p][0], l2 = c_path_l[p][1], l3 = c_path_l[p][2];
    const int d1 = 2*l1 + 1, d2 = 2*l2 + 1, d3 = 2*l3 + 1;
    const int n_el = d1 * d2 * d3;

    __shared__ double Ccg[125];
    __shared__ double Crr[125];
    __shared__ double q1r[25], q1i[25], q2r[25], q2i[25], q3r[25], q3i[25];
    __shared__ double red[64];

    int tid = threadIdx.x;  // 64 threads

    for (int idx = tid; idx < n_el; idx += 64) {
        int i  = idx / (d2*d3);
        int r  = idx % (d2*d3);
        int kq = r / d3;
        int nq = r % d3;
        Ccg[idx] = su2_cg(l1, i - l1, l2, kq - l2, l3, nq - l3);
    }
    if (tid == 0) qmat(l1, q1r, q1i);
    if (tid == 1) qmat(l2, q2r, q2i);
    if (tid == 2) qmat(l3, q3r, q3i);
    __syncthreads();

    double ss = 0.0;
    for (int idx = tid; idx < n_el; idx += 64) {
        int j  = idx / (d2*d3);
        int r  = idx % (d2*d3);
        int lc = r / d3;
        int m  = r % d3;
        double sre = 0.0;
        for (int i = 0; i < d1; i++)
            for (int kq = 0; kq < d2; kq++)
                for (int nq = 0; nq < d3; nq++) {
                    double c = Ccg[(i*d2 + kq)*d3 + nq];
                    if (c == 0.0) continue;
                    double ar = q1r[i*d1 + j],   ai = q1i[i*d1 + j];
                    double br = q2r[kq*d2 + lc], bi = q2i[kq*d2 + lc];
                    double cr = q3r[nq*d3 + m],  ci = q3i[nq*d3 + m];
                    double tr = ar*br - ai*bi;
                    double ti = ar*bi + ai*br;
                    sre += (tr*cr + ti*ci) * c;
                }
        Crr[idx] = sre;
        ss += sre * sre;
    }
    red[tid] = ss;
    __syncthreads();
    for (int s = 32; s > 0; s >>= 1) {
        if (tid < s) red[tid] += red[tid + s];
        __syncthreads();
    }
    double inv = rsqrt(red[0]);

    const int np = (d3 - 1) / 2;
    for (int e = tid; e < d1*d2; e += 64) {
        for (int pp = 0; pp < np; pp++) {
            g_w3j_pairs[(c_pair_off[p] + pp*d1*d2 + e)*2 + 0] = (float)(Crr[e*d3 + 2*pp    ] * inv);
            g_w3j_pairs[(c_pair_off[p] + pp*d1*d2 + e)*2 + 1] = (float)(Crr[e*d3 + 2*pp + 1] * inv);
        }
        g_w3j_last[c_last_off[p] + e] = (float)(Crr[e*d3 + (d3 - 1)] * inv);
    }
}

// ---------------------------------------------------------------------------
// Ownership-preserving butterfly reduction helpers (8 threads per node).
// Round order xor4, xor2, xor1 matches final w = 2t + lane ownership.
// ---------------------------------------------------------------------------
__device__ __forceinline__ void bf_round(float* f, int nvals, int half_stride,
                                         bool keep_low, int xr) {
    // f[0..nvals-1] valid in groups; pairs (i, i+half_stride) exchanged.
    #pragma unroll
    for (int i = 0; i < 16; i++) {
        if (i >= nvals) break;
    }
    (void)nvals; (void)half_stride; (void)keep_low; (void)xr;
}

// ---------------------------------------------------------------------------
// Per-path accumulation.
// ---------------------------------------------------------------------------
template<int L1, int L2, int L3, int BASE>
__device__ __forceinline__ void path_accum(
    const float* __restrict__ xn, const float* __restrict__ sW,
    const float* __restrict__ cgp, const float* __restrict__ cgl,
    int t, float* __restrict__ acc)
{
    constexpr int D1 = 2*L1 + 1, D2 = 2*L2 + 1, D3 = 2*L3 + 1;
    constexpr int NP = L3;                       // number of k-pairs
    constexpr int O1 = (L1 == 0) ? 0 : ((L1 == 1) ? 16 : 64);
    constexpr int O2 = (L2 == 0) ? 0 : ((L2 == 1) ? 16 : 64);

    const float* tW = sW + t * SW_STRIDE;        // row for v = t (+8 handled via +8*SW_STRIDE*?)
    const bool lo4 = ((t & 4) == 0);
    const bool lo2 = ((t & 2) == 0);
    const bool lo1 = ((t & 1) == 0);

    // ---- k-pair chunks (f32x2 packed over the two k's) ----
    #pragma unroll
    for (int p = 0; p < NP; p++) {
        const float* cg = cgp + p * (D1*D2) * 2;
        const int k0 = 2 * p;

        // a2[i*2+vi]: v = t + 8*vi
        unsigned long long a2[D1*2];
        #pragma unroll
        for (int q = 0; q < D1*2; q++) a2[q] = 0ull;
        #pragma unroll
        for (int j = 0; j < D2; j++) {
            unsigned long long x0 = dup2(xn[O2 + t*D2 + j]);
            unsigned long long x1 = dup2(xn[O2 + (t + 8)*D2 + j]);
            #pragma unroll
            for (int i = 0; i < D1; i++) {
                unsigned long long cp = *(const unsigned long long*)(cg + (i*D2 + j)*2);
                ffma2(a2[i*2 + 0], cp, x0);
                ffma2(a2[i*2 + 1], cp, x1);
            }
        }

        // A[k*8 + wp]: o[w=2wp..2wp+1, k0+k] partial over owned v's
        unsigned long long A[16];
        #pragma unroll
        for (int q = 0; q < 16; q++) A[q] = 0ull;

        #pragma unroll 4
        for (int u = 0; u < 16; u++) {
            unsigned long long xp[D1];
            #pragma unroll
            for (int i = 0; i < D1; i++) xp[i] = dup2(xn[O1 + u*D1 + i]);
            const float* uW = tW + u * (16 * SW_STRIDE);
            #pragma unroll
            for (int vi = 0; vi < 2; vi++) {
                unsigned long long b2 = 0ull;
                #pragma unroll
                for (int i = 0; i < D1; i++) ffma2(b2, xp[i], a2[i*2 + vi]);
                float b0, b1; unpack2(b2, b0, b1);
                unsigned long long b00 = dup2(b0), b11 = dup2(b1);
                const float* rW = uW + vi * (8 * SW_STRIDE);
                ulonglong2 wA = *(const ulonglong2*)(rW);
                ulonglong2 wB = *(const ulonglong2*)(rW + 4);
                ulonglong2 wC = *(const ulonglong2*)(rW + 8);
                ulonglong2 wD = *(const ulonglong2*)(rW + 12);
                ffma2(A[0], wA.x, b00);  ffma2(A[1], wA.y, b00);
                ffma2(A[2], wB.x, b00);  ffma2(A[3], wB.y, b00);
                ffma2(A[4], wC.x, b00);  ffma2(A[5], wC.y, b00);
                ffma2(A[6], wD.x, b00);  ffma2(A[7], wD.y, b00);
                ffma2(A[8],  wA.x, b11); ffma2(A[9],  wA.y, b11);
                ffma2(A[10], wB.x, b11); ffma2(A[11], wB.y, b11);
                ffma2(A[12], wC.x, b11); ffma2(A[13], wC.y, b11);
                ffma2(A[14], wD.x, b11); ffma2(A[15], wD.y, b11);
            }
        }

        // butterfly reduce across the 8 threads of this node
        float f[32];
        #pragma unroll
        for (int q = 0; q < 16; q++) unpack2(A[q], f[2*q], f[2*q + 1]);
        // R1: xor 4, keep wp half (0..3 vs 4..7), both k, both lanes
        #pragma unroll
        for (int k = 0; k < 2; k++)
            #pragma unroll
            for (int wp = 0; wp < 4; wp++)
                #pragma unroll
                for (int ln = 0; ln < 2; ln++) {
                    int iL = (k*8 + wp)*2 + ln, iH = (k*8 + wp + 4)*2 + ln;
                    float keep = lo4 ? f[iL] : f[iH];
                    float send = lo4 ? f[iH] : f[iL];
                    f[iL] = keep + __shfl_xor_sync(0xffffffffu, send, 4);
                }
        // R2: xor 2, local wp 0..1 vs 2..3
        #pragma unroll
        for (int k = 0; k < 2; k++)
            #pragma unroll
            for (int wp = 0; wp < 2; wp++)
                #pragma unroll
                for (int ln = 0; ln < 2; ln++) {
                    int iL = (k*8 + wp)*2 + ln, iH = (k*8 + wp + 2)*2 + ln;
                    float keep = lo2 ? f[iL] : f[iH];
                    float send = lo2 ? f[iH] : f[iL];
                    f[iL] = keep + __shfl_xor_sync(0xffffffffu, send, 2);
                }
        // R3: xor 1, local wp 0 vs 1
        #pragma unroll
        for (int k = 0; k < 2; k++)
            #pragma unroll
            for (int ln = 0; ln < 2; ln++) {
                int iL = (k*8)*2 + ln, iH = (k*8 + 1)*2 + ln;
                float keep = lo1 ? f[iL] : f[iH];
                float send = lo1 ? f[iH] : f[iL];
                f[iL] = keep + __shfl_xor_sync(0xffffffffu, send, 1);
            }
        acc[BASE + (k0 + 0)*2 + 0] += f[0];
        acc[BASE + (k0 + 0)*2 + 1] += f[1];
        acc[BASE + (k0 + 1)*2 + 0] += f[16];
        acc[BASE + (k0 + 1)*2 + 1] += f[17];
    }

    // ---- last (odd) k ----
    {
        constexpr int k = D3 - 1;
        float a1[D1*2];
        #pragma unroll
        for (int q = 0; q < D1*2; q++) a1[q] = 0.f;
        #pragma unroll
        for (int j = 0; j < D2; j++) {
            float xv0 = xn[O2 + t*D2 + j];
            float xv1 = xn[O2 + (t + 8)*D2 + j];
            #pragma unroll
            for (int i = 0; i < D1; i++) {
                float c = cgl[i*D2 + j];
                a1[i*2 + 0] = fmaf(c, xv0, a1[i*2 + 0]);
                a1[i*2 + 1] = fmaf(c, xv1, a1[i*2 + 1]);
            }
        }
        unsigned long long A1[8];
        #pragma unroll
        for (int q = 0; q < 8; q++) A1[q] = 0ull;
        #pragma unroll 4
        for (int u = 0; u < 16; u++) {
            float xr[D1];
            #pragma unroll
            for (int i = 0; i < D1; i++) xr[i] = xn[O1 + u*D1 + i];
            const float* uW = tW + u * (16 * SW_STRIDE);
            #pragma unroll
            for (int vi = 0; vi < 2; vi++) {
                float b = 0.f;
                #pragma unroll
                for (int i = 0; i < D1; i++) b = fmaf(xr[i], a1[i*2 + vi], b);
                unsigned long long bb = dup2(b);
                const float* rW = uW + vi * (8 * SW_STRIDE);
                ulonglong2 wA = *(const ulonglong2*)(rW);
                ulonglong2 wB = *(const ulonglong2*)(rW + 4);
                ulonglong2 wC = *(const ulonglong2*)(rW + 8);
                ulonglong2 wD = *(const ulonglong2*)(rW + 12);
                ffma2(A1[0], wA.x, bb); ffma2(A1[1], wA.y, bb);
                ffma2(A1[2], wB.x, bb); ffma2(A1[3], wB.y, bb);
                ffma2(A1[4], wC.x, bb); ffma2(A1[5], wC.y, bb);
                ffma2(A1[6], wD.x, bb); ffma2(A1[7], wD.y, bb);
            }
        }
        float f[16];
        #pragma unroll
        for (int q = 0; q < 8; q++) unpack2(A1[q], f[2*q], f[2*q + 1]);
        #pragma unroll
        for (int wp = 0; wp < 4; wp++)
            #pragma unroll
            for (int ln = 0; ln < 2; ln++) {
                int iL = wp*2 + ln, iH = (wp + 4)*2 + ln;
                float keep = lo4 ? f[iL] : f[iH];
                float send = lo4 ? f[iH] : f[iL];
                f[iL] = keep + __shfl_xor_sync(0xffffffffu, send, 4);
            }
        #pragma unroll
        for (int wp = 0; wp < 2; wp++)
            #pragma unroll
            for (int ln = 0; ln < 2; ln++) {
                int iL = wp*2 + ln, iH = (wp + 2)*2 + ln;
                float keep = lo2 ? f[iL] : f[iH];
                float send = lo2 ? f[iH] : f[iL];
                f[iL] = keep + __shfl_xor_sync(0xffffffffu, send, 2);
            }
        #pragma unroll
        for (int ln = 0; ln < 2; ln++) {
            int iL = ln, iH = 2 + ln;
            float keep = lo1 ? f[iL] : f[iH];
            float send = lo1 ? f[iH] : f[iL];
            f[iL] = keep + __shfl_xor_sync(0xffffffffu, send, 1);
        }
        acc[BASE + k*2 + 0] += f[0];
        acc[BASE + k*2 + 1] += f[1];
    }
}

__global__ void __launch_bounds__(CTA_THREADS, 2)
tfn_kernel(const float* __restrict__ x, const float* __restrict__ wv,
           float* __restrict__ out, int N)
{
    extern __shared__ float smem[];
    float* scg_pairs = smem;               // 248 floats (8B aligned at base)
    float* scg_last  = smem + 248;         // 115 floats
    float* xs        = smem + 364;         // 32*148
    float* sW        = smem + 364 + NODES_PER_CTA*XSTRIDE;   // 256*20

    const int tid = threadIdx.x;
    const int n0  = blockIdx.x * NODES_PER_CTA;

    for (int idx = tid; idx < NODES_PER_CTA * 36; idx += CTA_THREADS) {
        int n = idx / 36, fq = idx % 36;
        int gn = n0 + n;
        float4 v = (gn < N) ? ((const float4*)x)[gn*36 + fq]
                            : make_float4(0.f, 0.f, 0.f, 0.f);
        *(float4*)(xs + n*XSTRIDE + fq*4) = v;
    }
    for (int idx = tid; idx < 248; idx += CTA_THREADS) scg_pairs[idx] = g_w3j_pairs[idx];
    for (int idx = tid; idx < 115; idx += CTA_THREADS) scg_last[idx]  = g_w3j_last[idx];

    const int node = tid >> 3;
    const int t    = tid & 7;
    const float* xn = xs + node * XSTRIDE;

    // acc: l3=0 -> [0..1]; l3=1 -> [2 + k*2 + ln]; l3=2 -> [8 + k*2 + ln]
    float acc[18];
    #pragma unroll
    for (int i = 0; i < 18; i++) acc[i] = 0.f;

#define DO_PATH(P, L1v, L2v, L3v, BASEv, POFF, LOFF)                        \
    __syncthreads();                                                        \
    {                                                                       \
        const float4* wg = (const float4*)(wv + (P)*4096);                  \
        for (int idx = tid; idx < 1024; idx += CTA_THREADS) {               \
            float4 g = wg[idx];                                             \
            *(float4*)(sW + (idx >> 2)*SW_STRIDE + (idx & 3)*4) = g;        \
        }                                                                   \
    }                                                                       \
    __syncthreads();                                                        \
    path_accum<L1v, L2v, L3v, BASEv>(xn, sW, scg_pairs + 2*(POFF),          \
                                     scg_last + (LOFF), t, acc);

    DO_PATH(0,  0,0,0,  0,  0,  0)
    DO_PATH(1,  1,1,0,  0,  0,  1)
    DO_PATH(2,  2,2,0,  0,  0,  10)
    DO_PATH(3,  0,1,1,  2,  0,  35)
    DO_PATH(4,  1,0,1,  2,  3,  38)
    DO_PATH(5,  1,2,1,  2,  6,  41)
    DO_PATH(6,  2,1,1,  2,  21, 56)
    DO_PATH(7,  0,2,2,  8,  36, 71)
    DO_PATH(8,  1,1,2,  8,  46, 76)
    DO_PATH(9,  2,0,2,  8,  64, 85)
    DO_PATH(10, 2,2,2,  8,  74, 90)
#undef DO_PATH

    const int gn = n0 + node;
    if (gn < N) {
        const float sc0 = 0.03608439182435161f;   // sqrt(1/768)
        const float sc1 = 0.05412658773652741f;   // sqrt(3/1024)
        const float sc2 = 0.06987712429686843f;   // sqrt(5/1024)
        float* o = out + (size_t)gn * FEAT;
        #pragma unroll
        for (int ln = 0; ln < 2; ln++) {
            int w = 2*t + ln;
            float v = acc[ln] * sc0;
            o[w] = v > 0.f ? v : (expf(v) - 1.f);
        }
        #pragma unroll
        for (int k = 0; k < 3; k++)
            #pragma unroll
            for (int ln = 0; ln < 2; ln++) {
                int w = 2*t + ln;
                float v = acc[2 + k*2 + ln] * sc1;
                o[16 + w*3 + k] = v > 0.f ? v : (expf(v) - 1.f);
            }
        #pragma unroll
        for (int k = 0; k < 5; k++)
            #pragma unroll
            for (int ln = 0; ln < 2; ln++) {
                int w = 2*t + ln;
                float v = acc[8 + k*2 + ln] * sc2;
                o[64 + w*5 + k] = v > 0.f ? v : (expf(v) - 1.f);
            }
    }
}

// ---------------------------------------------------------------------------
extern "C" void kernel_launch(void* const* d_in, const int* in_sizes, int n_in,
                              void* d_out, int out_size)
{
    const float* x  = (const float*)d_in[0];   // nodes_features [N,144]
    const float* wv = (const float*)d_in[6];   // w_v [11,16,16,16]
    float* out = (float*)d_out;                // [9N,16] == [N,144]
    const int N = in_sizes[0] / FEAT;

    cudaFuncSetAttribute(tfn_kernel,
                         cudaFuncAttributeMaxDynamicSharedMemorySize, SMEM_BYTES);

    w3j_init_kernel<<<11, 64>>>();
    const int grid = (N + NODES_PER_CTA - 1) / NODES_PER_CTA;
    tfn_kernel<<<grid, CTA_THREADS, SMEM_BYTES>>>(x, wv, out, N);
}

// round 7
// speedup vs baseline: 2.0458x; 1.3236x over previous
#include <cuda_runtime.h>
#include <math.h>

// ============================================================================
// tensor_field_net — GB300
//
// attn = e/(e+1e-10), e=exp(d/12), d unit-scale => attn==1 to ~1e-9.
// So out = elu(FCTP(x,x,w_v)); q/k/dot skipped.
//
// R6: warp-per-node, all-k accumulation (W read from smem exactly once per
// node), XOR-swizzled W tiles (all 11 paths resident, 176KB), persistent CTAs,
// u-split b with shfl exchange, v-butterfly reduction.
// ============================================================================

#define FEAT           144
#define NODES_PER_CTA  16
#define CTA_THREADS    512
#define XSTRIDE        148
#define SMEM_FLOATS    (364 + NODES_PER_CTA*XSTRIDE + 11*4096)
#define SMEM_BYTES     (SMEM_FLOATS * 4)

__device__ float g_w3j_pairs[248];   // 124 float2, k-pair packed
__device__ float g_w3j_last[115];    // last (odd) k slice

__constant__ int c_path_l[11][3] = {
    {0,0,0},{1,1,0},{2,2,0},{0,1,1},{1,0,1},{1,2,1},{2,1,1},{0,2,2},{1,1,2},{2,0,2},{2,2,2}};
__constant__ int c_pair_off[11] = {0,0,0,0,3,6,21,36,46,64,74};     // float2 units
__constant__ int c_last_off[11] = {0,1,10,35,38,41,56,71,76,85,90};

// ---------------------------------------------------------------------------
// f32x2 helpers
// ---------------------------------------------------------------------------
__device__ __forceinline__ unsigned long long dup2(float v) {
    unsigned long long r;
    asm("mov.b64 %0, {%1, %1};" : "=l"(r) : "r"(__float_as_uint(v)));
    return r;
}
__device__ __forceinline__ void unpack2(unsigned long long p, float& lo, float& hi) {
    unsigned int a, b;
    asm("mov.b64 {%0, %1}, %2;" : "=r"(a), "=r"(b) : "l"(p));
    lo = __uint_as_float(a); hi = __uint_as_float(b);
}
__device__ __forceinline__ void ffma2(unsigned long long& acc,
                                      unsigned long long a, unsigned long long b) {
    asm("fma.rn.f32x2 %0, %1, %2, %0;" : "+l"(acc) : "l"(a), "l"(b));
}

// ---------------------------------------------------------------------------
// Wigner-3j init (fp64, faithful translation of the reference precompute)
// ---------------------------------------------------------------------------
__device__ double d_fact(int n) {
    double r = 1.0;
    for (int i = 2; i <= n; i++) r *= (double)i;
    return r;
}

__device__ double su2_cg(int j1, int m1, int j2, int m2, int j3, int m3) {
    if (m3 != m1 + m2) return 0.0;
    int vmin = max(max(-j1 + j2 + m3, -j1 + m1), 0);
    int vmax = min(min(j2 + j3 + m1, j3 - j1 + j2), j3 + m3);
    if (vmax < vmin) return 0.0;
    double C = sqrt((2.0*j3 + 1.0) * d_fact(j3 + j1 - j2) * d_fact(j3 - j1 + j2) *
                    d_fact(j1 + j2 - j3) * d_fact(j3 + m3) * d_fact(j3 - m3) /
                    (d_fact(j1 + j2 + j3 + 1) * d_fact(j1 - m1) * d_fact(j1 + m1) *
                     d_fact(j2 - m2) * d_fact(j2 + m2)));
    double S = 0.0;
    for (int v = vmin; v <= vmax; v++) {
        double term = d_fact(j2 + j3 + m1 - v) * d_fact(j1 - m1 + v) /
                      (d_fact(v) * d_fact(j3 - j1 + j2 - v) * d_fact(j3 + m3 - v) *
                       d_fact(v + j1 - j2 - m3));
        S += (((v + j2 + m2) & 1) ? -term : term);
    }
    return C * S;
}

__device__ void qmat(int l, double* qr, double* qi) {
    int d = 2*l + 1;
    for (int a = 0; a < d*d; a++) { qr[a] = 0.0; qi[a] = 0.0; }
    double s = 1.0 / sqrt(2.0);
    for (int m = -l; m < 0; m++) {
        qr[(l + m)*d + (l - m)] = s;
        qi[(l + m)*d + (l + m)] = -s;
    }
    qr[l*d + l] = 1.0;
    for (int m = 1; m <= l; m++) {
        double sg = (m & 1) ? -1.0 : 1.0;
        qr[(l + m)*d + (l + m)] = sg * s;
        qi[(l + m)*d + (l - m)] = sg * s;
    }
    int r = l & 3;
    double fr, fi;
    if      (r == 0) { fr = 1.0;  fi = 0.0;  }
    else if (r == 1) { fr = 0.0;  fi = -1.0; }
    else if (r == 2) { fr = -1.0; fi = 0.0;  }
    else             { fr = 0.0;  fi = 1.0;  }
    for (int a = 0; a < d*d; a++) {
        double nr = qr[a]*fr - qi[a]*fi;
        double ni = qr[a]*fi + qi[a]*fr;
        qr[a] = nr; qi[a] = ni;
    }
}

__global__ void w3j_init_kernel() {
    const int p  = blockIdx.x;
    const int l1 = c_path_l[p][0], l2 = c_path_l[p][1], l3 = c_path_l[p][2];
    const int d1 = 2*l1 + 1, d2 = 2*l2 + 1, d3 = 2*l3 + 1;
    const int n_el = d1 * d2 * d3;

    __shared__ double Ccg[125];
    __shared__ double Crr[125];
    __shared__ double q1r[25], q1i[25], q2r[25], q2i[25], q3r[25], q3i[25];
    __shared__ double red[64];

    int tid = threadIdx.x;  // 64 threads

    for (int idx = tid; idx < n_el; idx += 64) {
        int i  = idx / (d2*d3);
        int r  = idx % (d2*d3);
        int kq = r / d3;
        int nq = r % d3;
        Ccg[idx] = su2_cg(l1, i - l1, l2, kq - l2, l3, nq - l3);
    }
    if (tid == 0) qmat(l1, q1r, q1i);
    if (tid == 1) qmat(l2, q2r, q2i);
    if (tid == 2) qmat(l3, q3r, q3i);
    __syncthreads();

    double ss = 0.0;
    for (int idx = tid; idx < n_el; idx += 64) {
        int j  = idx / (d2*d3);
        int r  = idx % (d2*d3);
        int lc = r / d3;
        int m  = r % d3;
        double sre = 0.0;
        for (int i = 0; i < d1; i++)
            for (int kq = 0; kq < d2; kq++)
                for (int nq = 0; nq < d3; nq++) {
                    double c = Ccg[(i*d2 + kq)*d3 + nq];
                    if (c == 0.0) continue;
                    double ar = q1r[i*d1 + j],   ai = q1i[i*d1 + j];
                    double br = q2r[kq*d2 + lc], bi = q2i[kq*d2 + lc];
                    double cr = q3r[nq*d3 + m],  ci = q3i[nq*d3 + m];
                    double tr = ar*br - ai*bi;
                    double ti = ar*bi + ai*br;
                    sre += (tr*cr + ti*ci) * c;
                }
        Crr[idx] = sre;
        ss += sre * sre;
    }
    red[tid] = ss;
    __syncthreads();
    for (int s = 32; s > 0; s >>= 1) {
        if (tid < s) red[tid] += red[tid + s];
        __syncthreads();
    }
    double inv = rsqrt(red[0]);

    const int np = (d3 - 1) / 2;
    for (int e = tid; e < d1*d2; e += 64) {
        for (int pp = 0; pp < np; pp++) {
            g_w3j_pairs[(c_pair_off[p] + pp*d1*d2 + e)*2 + 0] = (float)(Crr[e*d3 + 2*pp    ] * inv);
            g_w3j_pairs[(c_pair_off[p] + pp*d1*d2 + e)*2 + 1] = (float)(Crr[e*d3 + 2*pp + 1] * inv);
        }
        g_w3j_last[c_last_off[p] + e] = (float)(Crr[e*d3 + (d3 - 1)] * inv);
    }
}

// ---------------------------------------------------------------------------
// Per-path accumulation. Warp = node. lane = wh*16 + v.
// Thread: owns v (a/b stage), u-half = wh (b compute), w-half = wh (acc).
// acc2[wp*D3 + k] packs output pair (w_local=2wp, 2wp+1), w = wh*8 + w_local.
// ---------------------------------------------------------------------------
template<int L1, int L2, int L3>
__device__ __forceinline__ void path_accum(
    const float* __restrict__ xn, const float* __restrict__ sWp,
    const float* __restrict__ cgp, const float* __restrict__ cgl,
    int v, int wh, unsigned long long* __restrict__ acc2)
{
    constexpr int D1 = 2*L1 + 1, D2 = 2*L2 + 1, D3 = 2*L3 + 1;
    constexpr int NP  = L3;                    // k-pairs
    constexpr int NPA = (NP > 0) ? NP : 1;
    constexpr int O1 = (L1 == 0) ? 0 : ((L1 == 1) ? 16 : 64);
    constexpr int O2 = (L2 == 0) ? 0 : ((L2 == 1) ? 16 : 64);

    // a[i][k] for my v:  pairs packed f32x2 + scalar last
    unsigned long long a2[D1*NPA];
    float al[D1];
    #pragma unroll
    for (int q = 0; q < D1*NPA; q++) a2[q] = 0ull;
    #pragma unroll
    for (int i = 0; i < D1; i++) al[i] = 0.f;

    #pragma unroll
    for (int j = 0; j < D2; j++) {
        float xv = xn[O2 + v*D2 + j];
        unsigned long long xd = dup2(xv);
        #pragma unroll
        for (int i = 0; i < D1; i++) {
            if (NP > 0) {
                #pragma unroll
                for (int p = 0; p < NP; p++) {
                    unsigned long long cp =
                        *(const unsigned long long*)(cgp + (p*D1*D2 + i*D2 + j)*2);
                    ffma2(a2[i*NPA + p], cp, xd);
                }
            }
            al[i] = fmaf(cgl[i*D2 + j], xv, al[i]);
        }
    }

    const int sw = (v >> 1) & 3;               // XOR chunk swizzle
    const int c0 = (((2*wh)     ^ sw) << 2);
    const int c1 = (((2*wh + 1) ^ sw) << 2);

    #pragma unroll
    for (int uu = 0; uu < 8; uu++) {
        const int u_m = wh*8 + uu;             // my u
        const int u_o = (wh ^ 1)*8 + uu;       // partner's u

        float x1[D1];
        #pragma unroll
        for (int i = 0; i < D1; i++) x1[i] = xn[O1 + u_m*D1 + i];

        float b[D3];
        if (NP > 0) {
            #pragma unroll
            for (int p = 0; p < NP; p++) {
                unsigned long long b2 = 0ull;
                #pragma unroll
                for (int i = 0; i < D1; i++) ffma2(b2, dup2(x1[i]), a2[i*NPA + p]);
                unpack2(b2, b[2*p], b[2*p + 1]);
            }
        }
        {
            float bl = 0.f;
            #pragma unroll
            for (int i = 0; i < D1; i++) bl = fmaf(x1[i], al[i], bl);
            b[D3 - 1] = bl;
        }
        float bo[D3];                          // partner's b (for u_o, my v)
        #pragma unroll
        for (int k = 0; k < D3; k++) bo[k] = __shfl_xor_sync(0xffffffffu, b[k], 16);

        const float* Wm = sWp + (u_m*16 + v)*16;
        const float* Wo = sWp + (u_o*16 + v)*16;
        ulonglong2 wmA = *(const ulonglong2*)(Wm + c0);   // w_local 0..3
        ulonglong2 wmB = *(const ulonglong2*)(Wm + c1);   // w_local 4..7
        ulonglong2 woA = *(const ulonglong2*)(Wo + c0);
        ulonglong2 woB = *(const ulonglong2*)(Wo + c1);
        #pragma unroll
        for (int k = 0; k < D3; k++) {
            unsigned long long bm = dup2(b[k]);
            ffma2(acc2[0*D3 + k], wmA.x, bm);
            ffma2(acc2[1*D3 + k], wmA.y, bm);
            ffma2(acc2[2*D3 + k], wmB.x, bm);
            ffma2(acc2[3*D3 + k], wmB.y, bm);
            unsigned long long bb = dup2(bo[k]);
            ffma2(acc2[0*D3 + k], woA.x, bb);
            ffma2(acc2[1*D3 + k], woA.y, bb);
            ffma2(acc2[2*D3 + k], woB.x, bb);
            ffma2(acc2[3*D3 + k], woB.y, bb);
        }
    }
}

// ---------------------------------------------------------------------------
// Butterfly reduction over the 16 v-lanes (x2 wh groups independent).
// Rounds xor8/xor4/xor2 split the 8 w's; xor1 splits k into [0,KLO) / [KLO,D3).
// ---------------------------------------------------------------------------
template<int D3>
__device__ __forceinline__ void reduce16(const unsigned long long* acc2, int lane,
                                         float* flo, float* fhi)
{
    constexpr int KHI = D3 / 2, KLO = D3 - KHI;
    float f[8*D3];
    #pragma unroll
    for (int wp = 0; wp < 4; wp++)
        #pragma unroll
        for (int k = 0; k < D3; k++)
            unpack2(acc2[wp*D3 + k], f[(2*wp)*D3 + k], f[(2*wp + 1)*D3 + k]);

    {   bool lo = (lane & 8) == 0;
        #pragma unroll
        for (int w = 0; w < 4; w++)
            #pragma unroll
            for (int k = 0; k < D3; k++) {
                int iL = w*D3 + k, iH = (w + 4)*D3 + k;
                float keep = lo ? f[iL] : f[iH];
                float send = lo ? f[iH] : f[iL];
                f[iL] = keep + __shfl_xor_sync(0xffffffffu, send, 8);
            }
    }
    {   bool lo = (lane & 4) == 0;
        #pragma unroll
        for (int w = 0; w < 2; w++)
            #pragma unroll
            for (int k = 0; k < D3; k++) {
                int iL = w*D3 + k, iH = (w + 2)*D3 + k;
                float keep = lo ? f[iL] : f[iH];
                float send = lo ? f[iH] : f[iL];
                f[iL] = keep + __shfl_xor_sync(0xffffffffu, send, 4);
            }
    }
    {   bool lo = (lane & 2) == 0;
        #pragma unroll
        for (int k = 0; k < D3; k++) {
            int iL = k, iH = D3 + k;
            float keep = lo ? f[iL] : f[iH];
            float send = lo ? f[iH] : f[iL];
            f[iL] = keep + __shfl_xor_sync(0xffffffffu, send, 2);
        }
    }
    {   bool lo = (lane & 1) == 0;
        #pragma unroll
        for (int q = 0; q < KLO; q++) {
            float send = lo ? ((q < KHI) ? f[KLO + q] : 0.f) : f[q];
            float r = __shfl_xor_sync(0xffffffffu, send, 1);
            flo[q] = f[q] + r;                   // valid on lanes with bit0==0, k=q
            if (q < KHI) fhi[q] = f[KLO + q] + r; // valid on lanes with bit0==1, k=KLO+q
        }
    }
}

__device__ __forceinline__ float elu1(float v) {
    return v > 0.f ? v : (expf(v) - 1.f);
}

// ---------------------------------------------------------------------------
__global__ void __launch_bounds__(CTA_THREADS, 1)
tfn_kernel(const float* __restrict__ x, const float* __restrict__ wv,
           float* __restrict__ out, int N, int numTiles)
{
    extern __shared__ float smem[];
    float* scg_pairs = smem;                       // 248
    float* scg_last  = smem + 248;                 // 115 (pad to 364)
    float* xs        = smem + 364;                 // 16*148
    float* sW        = smem + 364 + NODES_PER_CTA*XSTRIDE;   // 11*4096

    const int tid = threadIdx.x;

    for (int idx = tid; idx < 248; idx += CTA_THREADS) scg_pairs[idx] = g_w3j_pairs[idx];
    for (int idx = tid; idx < 115; idx += CTA_THREADS) scg_last[idx]  = g_w3j_last[idx];

    // Stage all 11 W tiles, XOR-swizzled on 16B chunks: chunk c -> c ^ ((v>>1)&3)
    for (int g = tid; g < 11*1024; g += CTA_THREADS) {
        int p = g >> 10, r = g & 1023;
        int u = r >> 6, rem = r & 63, v = rem >> 2, c = rem & 3;
        float4 val = ((const float4*)wv)[g];
        int dst = p*4096 + (u*16 + v)*16 + ((c ^ ((v >> 1) & 3)) << 2);
        *(float4*)(sW + dst) = val;
    }

    const int lane = tid & 31;
    const int wrp  = tid >> 5;
    const int v    = lane & 15;
    const int wh   = lane >> 4;
    const int wbit = wh*8 + ((lane & 8) ? 4 : 0) + ((lane & 4) ? 2 : 0) + ((lane & 2) ? 1 : 0);

    const float sc0 = 0.03608439182435161f;   // sqrt(1/768)
    const float sc1 = 0.05412658773652741f;   // sqrt(3/1024)
    const float sc2 = 0.06987712429686843f;   // sqrt(5/1024)

    for (int tile = blockIdx.x; tile < numTiles; tile += gridDim.x) {
        __syncthreads();   // xs reuse guard (also covers first-iter staging)
        for (int idx = tid; idx < NODES_PER_CTA*36; idx += CTA_THREADS) {
            int n = idx / 36, fq = idx % 36;
            int gn = tile*NODES_PER_CTA + n;
            float4 val = (gn < N) ? ((const float4*)x)[gn*36 + fq]
                                  : make_float4(0.f, 0.f, 0.f, 0.f);
            *(float4*)(xs + n*XSTRIDE + fq*4) = val;
        }
        __syncthreads();

        const float* xn = xs + wrp * XSTRIDE;
        const int gn = tile*NODES_PER_CTA + wrp;
        float* o = out + (size_t)gn * FEAT;
        const bool wr = (gn < N);
        const bool b0 = (lane & 1) == 0;

        // ---- l3 = 0 group (D3=1) ----
        {
            unsigned long long acc2[4] = {0ull, 0ull, 0ull, 0ull};
            path_accum<0,0,0>(xn, sW + 0*4096, scg_pairs, scg_last + 0,  v, wh, acc2);
            path_accum<1,1,0>(xn, sW + 1*4096, scg_pairs, scg_last + 1,  v, wh, acc2);
            path_accum<2,2,0>(xn, sW + 2*4096, scg_pairs, scg_last + 10, v, wh, acc2);
            float flo[1], fhi[1];
            reduce16<1>(acc2, lane, flo, fhi);
            if (wr && b0) o[wbit] = elu1(flo[0] * sc0);
        }
        // ---- l3 = 1 group (D3=3) ----
        {
            unsigned long long acc2[12];
            #pragma unroll
            for (int q = 0; q < 12; q++) acc2[q] = 0ull;
            path_accum<0,1,1>(xn, sW + 3*4096, scg_pairs + 2*0,  scg_last + 35, v, wh, acc2);
            path_accum<1,0,1>(xn, sW + 4*4096, scg_pairs + 2*3,  scg_last + 38, v, wh, acc2);
            path_accum<1,2,1>(xn, sW + 5*4096, scg_pairs + 2*6,  scg_last + 41, v, wh, acc2);
            path_accum<2,1,1>(xn, sW + 6*4096, scg_pairs + 2*21, scg_last + 56, v, wh, acc2);
            float flo[2], fhi[1];
            reduce16<3>(acc2, lane, flo, fhi);
            if (wr) {
                if (b0) {
                    o[16 + wbit*3 + 0] = elu1(flo[0] * sc1);
                    o[16 + wbit*3 + 1] = elu1(flo[1] * sc1);
                } else {
                    o[16 + wbit*3 + 2] = elu1(fhi[0] * sc1);
                }
            }
        }
        // ---- l3 = 2 group (D3=5) ----
        {
            unsigned long long acc2[20];
            #pragma unroll
            for (int q = 0; q < 20; q++) acc2[q] = 0ull;
            path_accum<0,2,2>(xn, sW + 7*4096,  scg_pairs + 2*36, scg_last + 71, v, wh, acc2);
            path_accum<1,1,2>(xn, sW + 8*4096,  scg_pairs + 2*46, scg_last + 76, v, wh, acc2);
            path_accum<2,0,2>(xn, sW + 9*4096,  scg_pairs + 2*64, scg_last + 85, v, wh, acc2);
            path_accum<2,2,2>(xn, sW + 10*4096, scg_pairs + 2*74, scg_last + 90, v, wh, acc2);
            float flo[3], fhi[2];
            reduce16<5>(acc2, lane, flo, fhi);
            if (wr) {
                if (b0) {
                    o[64 + wbit*5 + 0] = elu1(flo[0] * sc2);
                    o[64 + wbit*5 + 1] = elu1(flo[1] * sc2);
                    o[64 + wbit*5 + 2] = elu1(flo[2] * sc2);
                } else {
                    o[64 + wbit*5 + 3] = elu1(fhi[0] * sc2);
                    o[64 + wbit*5 + 4] = elu1(fhi[1] * sc2);
                }
            }
        }
    }
}

// ---------------------------------------------------------------------------
extern "C" void kernel_launch(void* const* d_in, const int* in_sizes, int n_in,
                              void* d_out, int out_size)
{
    const float* x  = (const float*)d_in[0];   // nodes_features [N,144]
    const float* wv = (const float*)d_in[6];   // w_v [11,16,16,16]
    float* out = (float*)d_out;                // [9N,16] == [N,144]
    const int N = in_sizes[0] / FEAT;
    const int numTiles = (N + NODES_PER_CTA - 1) / NODES_PER_CTA;

    cudaFuncSetAttribute(tfn_kernel,
                         cudaFuncAttributeMaxDynamicSharedMemorySize, SMEM_BYTES);

    w3j_init_kernel<<<11, 64>>>();
    tfn_kernel<<<148, CTA_THREADS, SMEM_BYTES>>>(x, wv, out, N, numTiles);
}

// round 8
// speedup vs baseline: 2.1052x; 1.0290x over previous
#include <cuda_runtime.h>
#include <math.h>

// ============================================================================
// tensor_field_net — GB300
//
// attn = e/(e+1e-10), e=exp(d/12), d unit-scale => attn==1 to ~1e-9.
// So out = elu(FCTP(x,x,w_v)); q/k/dot skipped.
//
// R7: warp = 2 nodes. Paths with l3<=1 run node-pair-packed in f32x2 (each
// smem W read serves both nodes -> W wavefronts halved for those paths).
// l3=2 group keeps the R6 scheme, executed once per node.
// ============================================================================

#define FEAT           144
#define NODES_PER_CTA  32
#define CTA_THREADS    512
#define XSTRIDE        148
#define SMEM_FLOATS    (364 + NODES_PER_CTA*XSTRIDE + 11*4096)
#define SMEM_BYTES     (SMEM_FLOATS * 4)

__device__ float g_w3j_pairs[248];   // 124 float2, k-pair packed
__device__ float g_w3j_last[115];    // last (odd) k slice

__constant__ int c_path_l[11][3] = {
    {0,0,0},{1,1,0},{2,2,0},{0,1,1},{1,0,1},{1,2,1},{2,1,1},{0,2,2},{1,1,2},{2,0,2},{2,2,2}};
__constant__ int c_pair_off[11] = {0,0,0,0,3,6,21,36,46,64,74};     // float2 units
__constant__ int c_last_off[11] = {0,1,10,35,38,41,56,71,76,85,90};

// ---------------------------------------------------------------------------
// f32x2 helpers
// ---------------------------------------------------------------------------
__device__ __forceinline__ unsigned long long pack2(float lo, float hi) {
    unsigned long long r;
    asm("mov.b64 %0, {%1, %2};" : "=l"(r)
        : "r"(__float_as_uint(lo)), "r"(__float_as_uint(hi)));
    return r;
}
__device__ __forceinline__ unsigned long long dup2(float v) {
    unsigned long long r;
    asm("mov.b64 %0, {%1, %1};" : "=l"(r) : "r"(__float_as_uint(v)));
    return r;
}
__device__ __forceinline__ void unpack2(unsigned long long p, float& lo, float& hi) {
    unsigned int a, b;
    asm("mov.b64 {%0, %1}, %2;" : "=r"(a), "=r"(b) : "l"(p));
    lo = __uint_as_float(a); hi = __uint_as_float(b);
}
__device__ __forceinline__ void ffma2(unsigned long long& acc,
                                      unsigned long long a, unsigned long long b) {
    asm("fma.rn.f32x2 %0, %1, %2, %0;" : "+l"(acc) : "l"(a), "l"(b));
}
__device__ __forceinline__ unsigned long long add2(unsigned long long a,
                                                   unsigned long long b) {
    unsigned long long r;
    asm("add.rn.f32x2 %0, %1, %2;" : "=l"(r) : "l"(a), "l"(b));
    return r;
}

// ---------------------------------------------------------------------------
// Wigner-3j init (fp64, faithful translation of the reference precompute)
// ---------------------------------------------------------------------------
__device__ double d_fact(int n) {
    double r = 1.0;
    for (int i = 2; i <= n; i++) r *= (double)i;
    return r;
}

__device__ double su2_cg(int j1, int m1, int j2, int m2, int j3, int m3) {
    if (m3 != m1 + m2) return 0.0;
    int vmin = max(max(-j1 + j2 + m3, -j1 + m1), 0);
    int vmax = min(min(j2 + j3 + m1, j3 - j1 + j2), j3 + m3);
    if (vmax < vmin) return 0.0;
    double C = sqrt((2.0*j3 + 1.0) * d_fact(j3 + j1 - j2) * d_fact(j3 - j1 + j2) *
                    d_fact(j1 + j2 - j3) * d_fact(j3 + m3) * d_fact(j3 - m3) /
                    (d_fact(j1 + j2 + j3 + 1) * d_fact(j1 - m1) * d_fact(j1 + m1) *
                     d_fact(j2 - m2) * d_fact(j2 + m2)));
    double S = 0.0;
    for (int v = vmin; v <= vmax; v++) {
        double term = d_fact(j2 + j3 + m1 - v) * d_fact(j1 - m1 + v) /
                      (d_fact(v) * d_fact(j3 - j1 + j2 - v) * d_fact(j3 + m3 - v) *
                       d_fact(v + j1 - j2 - m3));
        S += (((v + j2 + m2) & 1) ? -term : term);
    }
    return C * S;
}

__device__ void qmat(int l, double* qr, double* qi) {
    int d = 2*l + 1;
    for (int a = 0; a < d*d; a++) { qr[a] = 0.0; qi[a] = 0.0; }
    double s = 1.0 / sqrt(2.0);
    for (int m = -l; m < 0; m++) {
        qr[(l + m)*d + (l - m)] = s;
        qi[(l + m)*d + (l + m)] = -s;
    }
    qr[l*d + l] = 1.0;
    for (int m = 1; m <= l; m++) {
        double sg = (m & 1) ? -1.0 : 1.0;
        qr[(l + m)*d + (l + m)] = sg * s;
        qi[(l + m)*d + (l - m)] = sg * s;
    }
    int r = l & 3;
    double fr, fi;
    if      (r == 0) { fr = 1.0;  fi = 0.0;  }
    else if (r == 1) { fr = 0.0;  fi = -1.0; }
    else if (r == 2) { fr = -1.0; fi = 0.0;  }
    else             { fr = 0.0;  fi = 1.0;  }
    for (int a = 0; a < d*d; a++) {
        double nr = qr[a]*fr - qi[a]*fi;
        double ni = qr[a]*fi + qi[a]*fr;
        qr[a] = nr; qi[a] = ni;
    }
}

__global__ void w3j_init_kernel() {
    const int p  = blockIdx.x;
    const int l1 = c_path_l[p][0], l2 = c_path_l[p][1], l3 = c_path_l[p][2];
    const int d1 = 2*l1 + 1, d2 = 2*l2 + 1, d3 = 2*l3 + 1;
    const int n_el = d1 * d2 * d3;

    __shared__ double Ccg[125];
    __shared__ double Crr[125];
    __shared__ double q1r[25], q1i[25], q2r[25], q2i[25], q3r[25], q3i[25];
    __shared__ double red[64];

    int tid = threadIdx.x;  // 64 threads

    for (int idx = tid; idx < n_el; idx += 64) {
        int i  = idx / (d2*d3);
        int r  = idx % (d2*d3);
        int kq = r / d3;
        int nq = r % d3;
        Ccg[idx] = su2_cg(l1, i - l1, l2, kq - l2, l3, nq - l3);
    }
    if (tid == 0) qmat(l1, q1r, q1i);
    if (tid == 1) qmat(l2, q2r, q2i);
    if (tid == 2) qmat(l3, q3r, q3i);
    __syncthreads();

    double ss = 0.0;
    for (int idx = tid; idx < n_el; idx += 64) {
        int j  = idx / (d2*d3);
        int r  = idx % (d2*d3);
        int lc = r / d3;
        int m  = r % d3;
        double sre = 0.0;
        for (int i = 0; i < d1; i++)
            for (int kq = 0; kq < d2; kq++)
                for (int nq = 0; nq < d3; nq++) {
                    double c = Ccg[(i*d2 + kq)*d3 + nq];
                    if (c == 0.0) continue;
                    double ar = q1r[i*d1 + j],   ai = q1i[i*d1 + j];
                    double br = q2r[kq*d2 + lc], bi = q2i[kq*d2 + lc];
                    double cr = q3r[nq*d3 + m],  ci = q3i[nq*d3 + m];
                    double tr = ar*br - ai*bi;
                    double ti = ar*bi + ai*br;
                    sre += (tr*cr + ti*ci) * c;
                }
        Crr[idx] = sre;
        ss += sre * sre;
    }
    red[tid] = ss;
    __syncthreads();
    for (int s = 32; s > 0; s >>= 1) {
        if (tid < s) red[tid] += red[tid + s];
        __syncthreads();
    }
    double inv = rsqrt(red[0]);

    const int np = (d3 - 1) / 2;
    for (int e = tid; e < d1*d2; e += 64) {
        for (int pp = 0; pp < np; pp++) {
            g_w3j_pairs[(c_pair_off[p] + pp*d1*d2 + e)*2 + 0] = (float)(Crr[e*d3 + 2*pp    ] * inv);
            g_w3j_pairs[(c_pair_off[p] + pp*d1*d2 + e)*2 + 1] = (float)(Crr[e*d3 + 2*pp + 1] * inv);
        }
        g_w3j_last[c_last_off[p] + e] = (float)(Crr[e*d3 + (d3 - 1)] * inv);
    }
}

// ---------------------------------------------------------------------------
// Node-pair-packed path accumulation (l3 <= 1). Warp = 2 nodes.
// lane = wh*16 + v. acc2[wl*D3 + k] packs (node0, node1) for w = wh*8 + wl.
// ---------------------------------------------------------------------------
template<int L1, int L2, int L3>
__device__ __forceinline__ void path_accum_np(
    const float* __restrict__ xn0, const float* __restrict__ xn1,
    const float* __restrict__ sWp,
    const float* __restrict__ cgp, const float* __restrict__ cgl,
    int v, int wh, unsigned long long* __restrict__ acc2)
{
    constexpr int D1 = 2*L1 + 1, D2 = 2*L2 + 1, D3 = 2*L3 + 1;
    constexpr int NP = L3;                     // 0 or 1 here
    constexpr int O1 = (L1 == 0) ? 0 : ((L1 == 1) ? 16 : 64);
    constexpr int O2 = (L2 == 0) ? 0 : ((L2 == 1) ? 16 : 64);

    // a2[i*D3 + k] packed over (n0, n1)
    unsigned long long a2[D1*D3];
    #pragma unroll
    for (int q = 0; q < D1*D3; q++) a2[q] = 0ull;

    #pragma unroll
    for (int j = 0; j < D2; j++) {
        unsigned long long xp = pack2(xn0[O2 + v*D2 + j], xn1[O2 + v*D2 + j]);
        #pragma unroll
        for (int i = 0; i < D1; i++) {
            if (NP > 0) {
                float2 cc = *(const float2*)(cgp + (i*D2 + j)*2);
                ffma2(a2[i*D3 + 0], dup2(cc.x), xp);
                ffma2(a2[i*D3 + 1], dup2(cc.y), xp);
            }
            ffma2(a2[i*D3 + (D3 - 1)], dup2(cgl[i*D2 + j]), xp);
        }
    }

    const int sw = (v >> 1) & 3;
    const int c0 = (((2*wh)     ^ sw) << 2);
    const int c1 = (((2*wh + 1) ^ sw) << 2);

    #pragma unroll
    for (int uu = 0; uu < 8; uu++) {
        const int u_m = wh*8 + uu;
        const int u_o = (wh ^ 1)*8 + uu;

        unsigned long long b2[D3];
        #pragma unroll
        for (int k = 0; k < D3; k++) b2[k] = 0ull;
        #pragma unroll
        for (int i = 0; i < D1; i++) {
            unsigned long long xm = pack2(xn0[O1 + u_m*D1 + i], xn1[O1 + u_m*D1 + i]);
            #pragma unroll
            for (int k = 0; k < D3; k++) ffma2(b2[k], xm, a2[i*D3 + k]);
        }
        unsigned long long bo2[D3];
        #pragma unroll
        for (int k = 0; k < D3; k++)
            bo2[k] = __shfl_xor_sync(0xffffffffu, b2[k], 16);

        const float* Wm = sWp + (u_m*16 + v)*16;
        const float* Wo = sWp + (u_o*16 + v)*16;
        {
            float4 mA = *(const float4*)(Wm + c0);
            float4 mB = *(const float4*)(Wm + c1);
            unsigned long long dm[8] = {dup2(mA.x), dup2(mA.y), dup2(mA.z), dup2(mA.w),
                                        dup2(mB.x), dup2(mB.y), dup2(mB.z), dup2(mB.w)};
            #pragma unroll
            for (int k = 0; k < D3; k++)
                #pragma unroll
                for (int wl = 0; wl < 8; wl++)
                    ffma2(acc2[wl*D3 + k], dm[wl], b2[k]);
        }
        {
            float4 oA = *(const float4*)(Wo + c0);
            float4 oB = *(const float4*)(Wo + c1);
            unsigned long long dn[8] = {dup2(oA.x), dup2(oA.y), dup2(oA.z), dup2(oA.w),
                                        dup2(oB.x), dup2(oB.y), dup2(oB.z), dup2(oB.w)};
            #pragma unroll
            for (int k = 0; k < D3; k++)
                #pragma unroll
                for (int wl = 0; wl < 8; wl++)
                    ffma2(acc2[wl*D3 + k], dn[wl], bo2[k]);
        }
    }
}

// Packed butterfly over the 16 v-lanes. xor8/4/2 split the 8 w; xor1 splits k.
template<int D3>
__device__ __forceinline__ void reduce16_np(const unsigned long long* acc2, int lane,
                                            unsigned long long* flo,
                                            unsigned long long* fhi)
{
    constexpr int KHI = D3 / 2, KLO = D3 - KHI;
    unsigned long long f[8*D3];
    #pragma unroll
    for (int q = 0; q < 8*D3; q++) f[q] = acc2[q];

    {   bool lo = (lane & 8) == 0;
        #pragma unroll
        for (int w = 0; w < 4; w++)
            #pragma unroll
            for (int k = 0; k < D3; k++) {
                int iL = w*D3 + k, iH = (w + 4)*D3 + k;
                unsigned long long keep = lo ? f[iL] : f[iH];
                unsigned long long send = lo ? f[iH] : f[iL];
                f[iL] = add2(keep, __shfl_xor_sync(0xffffffffu, send, 8));
            }
    }
    {   bool lo = (lane & 4) == 0;
        #pragma unroll
        for (int w = 0; w < 2; w++)
            #pragma unroll
            for (int k = 0; k < D3; k++) {
                int iL = w*D3 + k, iH = (w + 2)*D3 + k;
                unsigned long long keep = lo ? f[iL] : f[iH];
                unsigned long long send = lo ? f[iH] : f[iL];
                f[iL] = add2(keep, __shfl_xor_sync(0xffffffffu, send, 4));
            }
    }
    {   bool lo = (lane & 2) == 0;
        #pragma unroll
        for (int k = 0; k < D3; k++) {
            int iL = k, iH = D3 + k;
            unsigned long long keep = lo ? f[iL] : f[iH];
            unsigned long long send = lo ? f[iH] : f[iL];
            f[iL] = add2(keep, __shfl_xor_sync(0xffffffffu, send, 2));
        }
    }
    {   bool lo = (lane & 1) == 0;
        #pragma unroll
        for (int q = 0; q < KLO; q++) {
            unsigned long long send = lo ? ((q < KHI) ? f[KLO + q] : 0ull) : f[q];
            unsigned long long r = __shfl_xor_sync(0xffffffffu, send, 1);
            flo[q] = add2(f[q], r);
            if (q < KHI) fhi[q] = add2(f[KLO + q], r);
        }
    }
}

// ---------------------------------------------------------------------------
// Scalar (single-node) accumulation for the l3 = 2 group — R6 scheme.
// ---------------------------------------------------------------------------
template<int L1, int L2, int L3>
__device__ __forceinline__ void path_accum(
    const float* __restrict__ xn, const float* __restrict__ sWp,
    const float* __restrict__ cgp, const float* __restrict__ cgl,
    int v, int wh, unsigned long long* __restrict__ acc2)
{
    constexpr int D1 = 2*L1 + 1, D2 = 2*L2 + 1, D3 = 2*L3 + 1;
    constexpr int NP  = L3;
    constexpr int NPA = (NP > 0) ? NP : 1;
    constexpr int O1 = (L1 == 0) ? 0 : ((L1 == 1) ? 16 : 64);
    constexpr int O2 = (L2 == 0) ? 0 : ((L2 == 1) ? 16 : 64);

    unsigned long long a2[D1*NPA];
    float al[D1];
    #pragma unroll
    for (int q = 0; q < D1*NPA; q++) a2[q] = 0ull;
    #pragma unroll
    for (int i = 0; i < D1; i++) al[i] = 0.f;

    #pragma unroll
    for (int j = 0; j < D2; j++) {
        float xv = xn[O2 + v*D2 + j];
        unsigned long long xd = dup2(xv);
        #pragma unroll
        for (int i = 0; i < D1; i++) {
            if (NP > 0) {
                #pragma unroll
                for (int p = 0; p < NP; p++) {
                    unsigned long long cp =
                        *(const unsigned long long*)(cgp + (p*D1*D2 + i*D2 + j)*2);
                    ffma2(a2[i*NPA + p], cp, xd);
                }
            }
            al[i] = fmaf(cgl[i*D2 + j], xv, al[i]);
        }
    }

    const int sw = (v >> 1) & 3;
    const int c0 = (((2*wh)     ^ sw) << 2);
    const int c1 = (((2*wh + 1) ^ sw) << 2);

    #pragma unroll
    for (int uu = 0; uu < 8; uu++) {
        const int u_m = wh*8 + uu;
        const int u_o = (wh ^ 1)*8 + uu;

        float x1[D1];
        #pragma unroll
        for (int i = 0; i < D1; i++) x1[i] = xn[O1 + u_m*D1 + i];

        float b[D3];
        if (NP > 0) {
            #pragma unroll
            for (int p = 0; p < NP; p++) {
                unsigned long long b2 = 0ull;
                #pragma unroll
                for (int i = 0; i < D1; i++) ffma2(b2, dup2(x1[i]), a2[i*NPA + p]);
                unpack2(b2, b[2*p], b[2*p + 1]);
            }
        }
        {
            float bl = 0.f;
            #pragma unroll
            for (int i = 0; i < D1; i++) bl = fmaf(x1[i], al[i], bl);
            b[D3 - 1] = bl;
        }
        float bo[D3];
        #pragma unroll
        for (int k = 0; k < D3; k++) bo[k] = __shfl_xor_sync(0xffffffffu, b[k], 16);

        const float* Wm = sWp + (u_m*16 + v)*16;
        const float* Wo = sWp + (u_o*16 + v)*16;
        ulonglong2 wmA = *(const ulonglong2*)(Wm + c0);
        ulonglong2 wmB = *(const ulonglong2*)(Wm + c1);
        ulonglong2 woA = *(const ulonglong2*)(Wo + c0);
        ulonglong2 woB = *(const ulonglong2*)(Wo + c1);
        #pragma unroll
        for (int k = 0; k < D3; k++) {
            unsigned long long bm = dup2(b[k]);
            ffma2(acc2[0*D3 + k], wmA.x, bm);
            ffma2(acc2[1*D3 + k], wmA.y, bm);
            ffma2(acc2[2*D3 + k], wmB.x, bm);
            ffma2(acc2[3*D3 + k], wmB.y, bm);
            unsigned long long bb = dup2(bo[k]);
            ffma2(acc2[0*D3 + k], woA.x, bb);
            ffma2(acc2[1*D3 + k], woA.y, bb);
            ffma2(acc2[2*D3 + k], woB.x, bb);
            ffma2(acc2[3*D3 + k], woB.y, bb);
        }
    }
}

template<int D3>
__device__ __forceinline__ void reduce16(const unsigned long long* acc2, int lane,
                                         float* flo, float* fhi)
{
    constexpr int KHI = D3 / 2, KLO = D3 - KHI;
    float f[8*D3];
    #pragma unroll
    for (int wp = 0; wp < 4; wp++)
        #pragma unroll
        for (int k = 0; k < D3; k++)
            unpack2(acc2[wp*D3 + k], f[(2*wp)*D3 + k], f[(2*wp + 1)*D3 + k]);

    {   bool lo = (lane & 8) == 0;
        #pragma unroll
        for (int w = 0; w < 4; w++)
            #pragma unroll
            for (int k = 0; k < D3; k++) {
                int iL = w*D3 + k, iH = (w + 4)*D3 + k;
                float keep = lo ? f[iL] : f[iH];
                float send = lo ? f[iH] : f[iL];
                f[iL] = keep + __shfl_xor_sync(0xffffffffu, send, 8);
            }
    }
    {   bool lo = (lane & 4) == 0;
        #pragma unroll
        for (int w = 0; w < 2; w++)
            #pragma unroll
            for (int k = 0; k < D3; k++) {
                int iL = w*D3 + k, iH = (w + 2)*D3 + k;
                float keep = lo ? f[iL] : f[iH];
                float send = lo ? f[iH] : f[iL];
                f[iL] = keep + __shfl_xor_sync(0xffffffffu, send, 4);
            }
    }
    {   bool lo = (lane & 2) == 0;
        #pragma unroll
        for (int k = 0; k < D3; k++) {
            int iL = k, iH = D3 + k;
            float keep = lo ? f[iL] : f[iH];
            float send = lo ? f[iH] : f[iL];
            f[iL] = keep + __shfl_xor_sync(0xffffffffu, send, 2);
        }
    }
    {   bool lo = (lane & 1) == 0;
        #pragma unroll
        for (int q = 0; q < KLO; q++) {
            float send = lo ? ((q < KHI) ? f[KLO + q] : 0.f) : f[q];
            float r = __shfl_xor_sync(0xffffffffu, send, 1);
            flo[q] = f[q] + r;
            if (q < KHI) fhi[q] = f[KLO + q] + r;
        }
    }
}

__device__ __forceinline__ float elu1(float v) {
    return v > 0.f ? v : (expf(v) - 1.f);
}

// ---------------------------------------------------------------------------
__global__ void __launch_bounds__(CTA_THREADS, 1)
tfn_kernel(const float* __restrict__ x, const float* __restrict__ wv,
           float* __restrict__ out, int N, int numTiles)
{
    extern __shared__ float smem[];
    float* scg_pairs = smem;                       // 248
    float* scg_last  = smem + 248;                 // 115 (pad to 364)
    float* xs        = smem + 364;                 // 32*148
    float* sW        = smem + 364 + NODES_PER_CTA*XSTRIDE;   // 11*4096

    const int tid = threadIdx.x;

    for (int idx = tid; idx < 248; idx += CTA_THREADS) scg_pairs[idx] = g_w3j_pairs[idx];
    for (int idx = tid; idx < 115; idx += CTA_THREADS) scg_last[idx]  = g_w3j_last[idx];

    // Stage all 11 W tiles, XOR-swizzled on 16B chunks: chunk c -> c ^ ((v>>1)&3)
    for (int g = tid; g < 11*1024; g += CTA_THREADS) {
        int p = g >> 10, r = g & 1023;
        int u = r >> 6, rem = r & 63, v = rem >> 2, c = rem & 3;
        float4 val = ((const float4*)wv)[g];
        int dst = p*4096 + (u*16 + v)*16 + ((c ^ ((v >> 1) & 3)) << 2);
        *(float4*)(sW + dst) = val;
    }

    const int lane = tid & 31;
    const int wrp  = tid >> 5;
    const int v    = lane & 15;
    const int wh   = lane >> 4;
    const int wbit = wh*8 + ((lane & 8) ? 4 : 0) + ((lane & 4) ? 2 : 0) + ((lane & 2) ? 1 : 0);

    const float sc0 = 0.03608439182435161f;   // sqrt(1/768)
    const float sc1 = 0.05412658773652741f;   // sqrt(3/1024)
    const float sc2 = 0.06987712429686843f;   // sqrt(5/1024)

    for (int tile = blockIdx.x; tile < numTiles; tile += gridDim.x) {
        __syncthreads();   // xs reuse guard (also covers first-iter staging)
        for (int idx = tid; idx < NODES_PER_CTA*36; idx += CTA_THREADS) {
            int n = idx / 36, fq = idx % 36;
            int gn = tile*NODES_PER_CTA + n;
            float4 val = (gn < N) ? ((const float4*)x)[gn*36 + fq]
                                  : make_float4(0.f, 0.f, 0.f, 0.f);
            *(float4*)(xs + n*XSTRIDE + fq*4) = val;
        }
        __syncthreads();

        const int gn0 = tile*NODES_PER_CTA + wrp*2;
        const int gn1 = gn0 + 1;
        const float* xn0 = xs + (wrp*2    ) * XSTRIDE;
        const float* xn1 = xs + (wrp*2 + 1) * XSTRIDE;
        float* o0 = out + (size_t)gn0 * FEAT;
        float* o1 = out + (size_t)gn1 * FEAT;
        const bool wr0 = (gn0 < N), wr1 = (gn1 < N);
        const bool b0 = (lane & 1) == 0;

        // ---- l3 = 0 group (node-pair packed) ----
        {
            unsigned long long acc2[8];
            #pragma unroll
            for (int q = 0; q < 8; q++) acc2[q] = 0ull;
            path_accum_np<0,0,0>(xn0, xn1, sW + 0*4096, scg_pairs, scg_last + 0,  v, wh, acc2);
            path_accum_np<1,1,0>(xn0, xn1, sW + 1*4096, scg_pairs, scg_last + 1,  v, wh, acc2);
            path_accum_np<2,2,0>(xn0, xn1, sW + 2*4096, scg_pairs, scg_last + 10, v, wh, acc2);
            unsigned long long flo[1], fhi[1];
            reduce16_np<1>(acc2, lane, flo, fhi);
            if (b0) {
                float f0, f1; unpack2(flo[0], f0, f1);
                if (wr0) o0[wbit] = elu1(f0 * sc0);
                if (wr1) o1[wbit] = elu1(f1 * sc0);
            }
        }
        // ---- l3 = 1 group (node-pair packed) ----
        {
            unsigned long long acc2[24];
            #pragma unroll
            for (int q = 0; q < 24; q++) acc2[q] = 0ull;
            path_accum_np<0,1,1>(xn0, xn1, sW + 3*4096, scg_pairs + 2*0,  scg_last + 35, v, wh, acc2);
            path_accum_np<1,0,1>(xn0, xn1, sW + 4*4096, scg_pairs + 2*3,  scg_last + 38, v, wh, acc2);
            path_accum_np<1,2,1>(xn0, xn1, sW + 5*4096, scg_pairs + 2*6,  scg_last + 41, v, wh, acc2);
            path_accum_np<2,1,1>(xn0, xn1, sW + 6*4096, scg_pairs + 2*21, scg_last + 56, v, wh, acc2);
            unsigned long long flo[2], fhi[1];
            reduce16_np<3>(acc2, lane, flo, fhi);
            if (b0) {
                #pragma unroll
                for (int q = 0; q < 2; q++) {
                    float f0, f1; unpack2(flo[q], f0, f1);
                    if (wr0) o0[16 + wbit*3 + q] = elu1(f0 * sc1);
                    if (wr1) o1[16 + wbit*3 + q] = elu1(f1 * sc1);
                }
            } else {
                float f0, f1; unpack2(fhi[0], f0, f1);
                if (wr0) o0[16 + wbit*3 + 2] = elu1(f0 * sc1);
                if (wr1) o1[16 + wbit*3 + 2] = elu1(f1 * sc1);
            }
        }
        // ---- l3 = 2 group (scalar, once per node) ----
        #pragma unroll 1
        for (int nn = 0; nn < 2; nn++) {
            const float* xn = (nn == 0) ? xn0 : xn1;
            float* o = (nn == 0) ? o0 : o1;
            const bool wr = (nn == 0) ? wr0 : wr1;

            unsigned long long acc2[20];
            #pragma unroll
            for (int q = 0; q < 20; q++) acc2[q] = 0ull;
            path_accum<0,2,2>(xn, sW + 7*4096,  scg_pairs + 2*36, scg_last + 71, v, wh, acc2);
            path_accum<1,1,2>(xn, sW + 8*4096,  scg_pairs + 2*46, scg_last + 76, v, wh, acc2);
            path_accum<2,0,2>(xn, sW + 9*4096,  scg_pairs + 2*64, scg_last + 85, v, wh, acc2);
            path_accum<2,2,2>(xn, sW + 10*4096, scg_pairs + 2*74, scg_last + 90, v, wh, acc2);
            float flo[3], fhi[2];
            reduce16<5>(acc2, lane, flo, fhi);
            if (wr) {
                if (b0) {
                    o[64 + wbit*5 + 0] = elu1(flo[0] * sc2);
                    o[64 + wbit*5 + 1] = elu1(flo[1] * sc2);
                    o[64 + wbit*5 + 2] = elu1(flo[2] * sc2);
                } else {
                    o[64 + wbit*5 + 3] = elu1(fhi[0] * sc2);
                    o[64 + wbit*5 + 4] = elu1(fhi[1] * sc2);
                }
            }
        }
    }
}

// ---------------------------------------------------------------------------
extern "C" void kernel_launch(void* const* d_in, const int* in_sizes, int n_in,
                              void* d_out, int out_size)
{
    const float* x  = (const float*)d_in[0];   // nodes_features [N,144]
    const float* wv = (const float*)d_in[6];   // w_v [11,16,16,16]
    float* out = (float*)d_out;                // [9N,16] == [N,144]
    const int N = in_sizes[0] / FEAT;
    const int numTiles = (N + NODES_PER_CTA - 1) / NODES_PER_CTA;

    cudaFuncSetAttribute(tfn_kernel,
                         cudaFuncAttributeMaxDynamicSharedMemorySize, SMEM_BYTES);

    w3j_init_kernel<<<11, 64>>>();
    tfn_kernel<<<148, CTA_THREADS, SMEM_BYTES>>>(x, wv, out, N, numTiles);
}